// round 8
// baseline (speedup 1.0000x reference)
#include <cuda_runtime.h>
#include <cuda_fp16.h>
#include <math.h>
#include <stdint.h>

#define BB 64
#define SS 1024
#define EE 1024
#define DD 512

// ---------------- device scratch ----------------
__device__ float  g_hp[BB * DD];            // h_proj + bias  [B, D]
__device__ __half g_ench[(size_t)BB * SS * EE];  // enc in fp16 (134 MB)
__device__ __half g_WeTh[DD * EE];          // W_e^T in fp16 [D(n), E2(k)]
__device__ float  g_pscore[2 * BB * SS];    // per-n-tile score partials
__device__ float  g_ctx_part[8 * BB * EE];  // context partials

// ---------------- helpers ----------------
__device__ __forceinline__ uint32_t smem_u32(const void* p) {
    uint32_t a;
    asm("{ .reg .u64 t; cvta.to.shared.u64 t, %1; cvt.u32.u64 %0, t; }" : "=r"(a) : "l"(p));
    return a;
}
#define CP_ASYNC16(dst, src) \
    asm volatile("cp.async.cg.shared.global [%0], [%1], 16;" :: "r"(dst), "l"(src) : "memory")
#define CP_COMMIT() asm volatile("cp.async.commit_group;" ::: "memory")
#define CP_WAIT3()  asm volatile("cp.async.wait_group 3;" ::: "memory")
#define CP_WAIT0()  asm volatile("cp.async.wait_group 0;" ::: "memory")

__device__ __forceinline__ uint32_t pack_half2(float lo, float hi) {
    uint32_t r;
    asm("cvt.rn.f16x2.f32 %0, %1, %2;" : "=r"(r) : "f"(hi), "f"(lo));
    return r;
}

__device__ __forceinline__ void mma_f16(float c[4], uint32_t a0, uint32_t a1,
                                        uint32_t a2, uint32_t a3, uint32_t b0,
                                        uint32_t b1) {
    asm volatile(
        "mma.sync.aligned.m16n8k16.row.col.f32.f16.f16.f32 "
        "{%0,%1,%2,%3}, {%4,%5,%6,%7}, {%8,%9}, {%0,%1,%2,%3};"
        : "+f"(c[0]), "+f"(c[1]), "+f"(c[2]), "+f"(c[3])
        : "r"(a0), "r"(a1), "r"(a2), "r"(a3), "r"(b0), "r"(b1));
}

// ---------------- tiling ----------------
#define BM 128
#define BN 256
#define BK 32
#define NCHUNK (EE / BK)        // 32
#define NSTAGE 4
#define RSB 80                  // row stride BYTES (64 data + 16 pad)
#define A_SZB (BM * RSB)        // 10240
#define B_SZB (BN * RSB)        // 20480
#define STAGE_B (A_SZB + B_SZB) // 30720
#define OFF_SHP (NSTAGE * STAGE_B)            // 122880: hp tile (256 floats)
#define OFF_SV  (OFF_SHP + BN * 4)            // v tile (256 floats)
#define OFF_RED 0                             // red[128][17] aliases stage 0 (dead)
#define SMEM_SIZE (OFF_SV + BN * 4)           // 124928 B

// ---------------------------------------------------------------------------
// convert enc f32 -> fp16. grid 32768 x 256 thr, 8 elems/thread.
// ---------------------------------------------------------------------------
__global__ void __launch_bounds__(256) convert_enc(const float* __restrict__ enc) {
    size_t base = ((size_t)blockIdx.x * 256 + threadIdx.x) * 8;
    float4 v0 = *(const float4*)(enc + base);
    float4 v1 = *(const float4*)(enc + base + 4);
    uint4 o;
    o.x = pack_half2(v0.x, v0.y);
    o.y = pack_half2(v0.z, v0.w);
    o.z = pack_half2(v1.x, v1.y);
    o.w = pack_half2(v1.z, v1.w);
    *(uint4*)(&g_ench[base]) = o;
}

// ---------------------------------------------------------------------------
// transpose W_e [E2, D] -> g_WeTh [D, E2] fp16 (rn)
// ---------------------------------------------------------------------------
__global__ void transpose_we(const float* __restrict__ attn_W) {
    __shared__ float t[32][33];
    int k0 = blockIdx.x * 32, d0 = blockIdx.y * 32;
    for (int i = threadIdx.y; i < 32; i += 8)
        t[i][threadIdx.x] = attn_W[(size_t)(DD + k0 + i) * DD + d0 + threadIdx.x];
    __syncthreads();
    for (int i = threadIdx.y; i < 32; i += 8)
        g_WeTh[(size_t)(d0 + i) * EE + k0 + threadIdx.x] = __float2half_rn(t[threadIdx.x][i]);
}

// ---------------------------------------------------------------------------
// hp[b,d] = attn_b[d] + hidden[b,:] @ attn_W[:D, d]   (exact fp32)
// ---------------------------------------------------------------------------
__global__ void hproj_kernel(const float* __restrict__ hidden,
                             const float* __restrict__ attn_W,
                             const float* __restrict__ attn_b) {
    __shared__ float hrow[DD];
    int b = blockIdx.y;
    int d = blockIdx.x * 128 + threadIdx.x;
    for (int i = threadIdx.x; i < DD; i += 128) hrow[i] = hidden[b * DD + i];
    __syncthreads();
    float acc = attn_b[d];
#pragma unroll 8
    for (int k = 0; k < DD; k++) acc += hrow[k] * attn_W[k * DD + d];
    g_hp[b * DD + d] = acc;
}

// ---------------------------------------------------------------------------
// scores: fp16 m16n8k16 GEMM (128x256 tile, K=1024), 4-stage cp.async.
// 512 threads / 16 warps (4m x 4n), warp tile 32x64 -> ~112 regs/thread,
// 4 warps/SMSP for latency hiding. k-slot permutation as before.
// grid (2 n-tiles, 512 row-tiles).
// ---------------------------------------------------------------------------
__global__ void __launch_bounds__(512, 1)
scores_mma_kernel(const float* __restrict__ vW) {
    extern __shared__ char smem[];
    uint32_t sb = smem_u32(smem);
    int tid = threadIdx.x;
    int wid = tid >> 5, lid = tid & 31;
    int gid = lid >> 2, tig = lid & 3;
    int wm = wid >> 2, wn = wid & 3;       // warp grid 4(m) x 4(n)
    int nt = blockIdx.x;                   // n tile (0..1)
    int r0 = blockIdx.y * BM;              // global row
    int b = r0 / SS;
    int n0 = nt * BN;

    float* shp = (float*)(smem + OFF_SHP);
    float* sv  = (float*)(smem + OFF_SV);
    for (int i = tid; i < BN; i += 512) {
        shp[i] = g_hp[b * DD + n0 + i];
        sv[i]  = vW[n0 + i];
    }

    const __half* Abase = g_ench + (size_t)r0 * EE;
    const __half* Bbase = g_WeTh + (size_t)n0 * EE;

    auto load_chunk = [&](int c, int st) {
        uint32_t sA = sb + st * STAGE_B;
        uint32_t sB = sA + A_SZB;
        {                                             // A: 512 16B chunks
            int row = tid >> 2, ch = tid & 3;
            CP_ASYNC16(sA + row * RSB + ch * 16,
                       Abase + (size_t)row * EE + c * BK + ch * 8);
        }
#pragma unroll
        for (int i = 0; i < 2; i++) {                 // B: 1024 16B chunks
            int idx = tid + i * 512;
            int row = idx >> 2, ch = idx & 3;
            CP_ASYNC16(sB + row * RSB + ch * 16,
                       Bbase + (size_t)row * EE + c * BK + ch * 8);
        }
        CP_COMMIT();
    };

    float acc[2][8][4];
#pragma unroll
    for (int mf = 0; mf < 2; mf++)
#pragma unroll
        for (int nf = 0; nf < 8; nf++)
#pragma unroll
            for (int q = 0; q < 4; q++) acc[mf][nf][q] = 0.f;

    load_chunk(0, 0);
    load_chunk(1, 1);
    load_chunk(2, 2);
    load_chunk(3, 3);

    int st = 0;
    for (int c = 0; c < NCHUNK; c++) {
        CP_WAIT3();
        __syncthreads();
        const char* fA = smem + st * STAGE_B;
        const char* fB = smem + st * STAGE_B + A_SZB;

        uint4 alo[2], ahi[2], bv[8];   // 8 halves each: phys k = 8*tig..+7
#pragma unroll
        for (int mf = 0; mf < 2; mf++) {
            int m0 = wm * 32 + mf * 16 + gid;
            alo[mf] = *(const uint4*)(fA + m0 * RSB + tig * 16);
            ahi[mf] = *(const uint4*)(fA + (m0 + 8) * RSB + tig * 16);
        }
#pragma unroll
        for (int nf = 0; nf < 8; nf++) {
            int nr = wn * 64 + nf * 8 + gid;
            bv[nf] = *(const uint4*)(fB + nr * RSB + tig * 16);
        }
        // instr 0: half-pairs 0,1 (phys k 8t..8t+3)
#pragma unroll
        for (int mf = 0; mf < 2; mf++)
#pragma unroll
            for (int nf = 0; nf < 8; nf++)
                mma_f16(acc[mf][nf], alo[mf].x, ahi[mf].x, alo[mf].y, ahi[mf].y,
                        bv[nf].x, bv[nf].y);
        // instr 1: half-pairs 2,3 (phys k 8t+4..8t+7)
#pragma unroll
        for (int mf = 0; mf < 2; mf++)
#pragma unroll
            for (int nf = 0; nf < 8; nf++)
                mma_f16(acc[mf][nf], alo[mf].z, ahi[mf].z, alo[mf].w, ahi[mf].w,
                        bv[nf].z, bv[nf].w);

        __syncthreads();
        if (c + NSTAGE < NCHUNK) load_chunk(c + NSTAGE, st);
        st = (st == NSTAGE - 1) ? 0 : st + 1;
    }
    CP_WAIT0();
    __syncthreads();   // stages dead; red aliases stage 0

    // ---- epilogue: score partial = sum_n v[n] * tanh(acc + hp[n]) ----
    float* red = (float*)(smem + OFF_RED);  // [128][17]
#pragma unroll
    for (int mf = 0; mf < 2; mf++) {
#pragma unroll
        for (int half = 0; half < 2; half++) {
            int r = wm * 32 + mf * 16 + half * 8 + gid;
            float s = 0.f;
#pragma unroll
            for (int nf = 0; nf < 8; nf++) {
                int nl = wn * 64 + nf * 8 + tig * 2;
                float e0 = acc[mf][nf][half * 2 + 0] + shp[nl];
                float e1 = acc[mf][nf][half * 2 + 1] + shp[nl + 1];
                float t0, t1;
                asm("tanh.approx.f32 %0, %1;" : "=f"(t0) : "f"(e0));
                asm("tanh.approx.f32 %0, %1;" : "=f"(t1) : "f"(e1));
                s = fmaf(sv[nl], t0, s);
                s = fmaf(sv[nl + 1], t1, s);
            }
            red[r * 17 + wn * 4 + tig] = s;
        }
    }
    __syncthreads();
    if (tid < BM) {
        float s = 0.f;
#pragma unroll
        for (int t = 0; t < 16; t++) s += red[tid * 17 + t];
        g_pscore[nt * (BB * SS) + r0 + tid] = s;
    }
}

// ---------------------------------------------------------------------------
// softmax: combine 2 partials, mask, softmax over S. grid(64), 256 threads.
// ---------------------------------------------------------------------------
__global__ void softmax_kernel(const int* __restrict__ mask,
                               float* __restrict__ wout) {
    int b = blockIdx.x;
    __shared__ float sc[SS];
    __shared__ float redbuf[256];
    int tid = threadIdx.x;

    float lmax = -3.402823466e38f;
    for (int s = tid; s < SS; s += 256) {
        int idx = b * SS + s;
        float v = g_pscore[idx] + g_pscore[BB * SS + idx];
        if (mask[idx] == 0) v = -3.402823466e38f;
        sc[s] = v;
        lmax = fmaxf(lmax, v);
    }
    redbuf[tid] = lmax;
    __syncthreads();
    for (int o = 128; o > 0; o >>= 1) {
        if (tid < o) redbuf[tid] = fmaxf(redbuf[tid], redbuf[tid + o]);
        __syncthreads();
    }
    float m = redbuf[0];
    __syncthreads();

    float lsum = 0.f;
    for (int s = tid; s < SS; s += 256) {
        float e = expf(sc[s] - m);
        sc[s] = e;
        lsum += e;
    }
    redbuf[tid] = lsum;
    __syncthreads();
    for (int o = 128; o > 0; o >>= 1) {
        if (tid < o) redbuf[tid] += redbuf[tid + o];
        __syncthreads();
    }
    float inv = 1.f / redbuf[0];
    for (int s = tid; s < SS; s += 256) wout[b * SS + s] = sc[s] * inv;
}

// ---------------------------------------------------------------------------
// context partials: grid (2, 8, 64), 128 threads; float4 per thread.
// ---------------------------------------------------------------------------
__global__ void __launch_bounds__(128) context_part_kernel(
    const float* __restrict__ enc, const float* __restrict__ w) {
    __shared__ float ws[128];
    int bx = blockIdx.x, sy = blockIdx.y, b = blockIdx.z;
    int e0 = bx * 512 + threadIdx.x * 4;
    ws[threadIdx.x] = w[b * SS + sy * 128 + threadIdx.x];
    __syncthreads();
    const float* base = enc + ((size_t)b * SS + sy * 128) * EE + e0;
    float4 acc = make_float4(0.f, 0.f, 0.f, 0.f);
#pragma unroll 8
    for (int r = 0; r < 128; r++) {
        float4 v = *(const float4*)(base + (size_t)r * EE);
        float c = ws[r];
        acc.x = fmaf(c, v.x, acc.x);
        acc.y = fmaf(c, v.y, acc.y);
        acc.z = fmaf(c, v.z, acc.z);
        acc.w = fmaf(c, v.w, acc.w);
    }
    *(float4*)&g_ctx_part[((size_t)sy * BB + b) * EE + e0] = acc;
}

__global__ void context_reduce_kernel(float* __restrict__ ctx) {
    int b = blockIdx.y;
    int e = blockIdx.x * 256 + threadIdx.x;
    float s = 0.f;
#pragma unroll
    for (int sy = 0; sy < 8; sy++) s += g_ctx_part[((size_t)sy * BB + b) * EE + e];
    ctx[b * EE + e] = s;
}

// ---------------------------------------------------------------------------
extern "C" void kernel_launch(void* const* d_in, const int* in_sizes, int n_in,
                              void* d_out, int out_size) {
    const float* hidden = (const float*)d_in[0];   // [B, D]
    const float* enc    = (const float*)d_in[1];   // [B, S, E2]
    const int*   mask   = (const int*)d_in[2];     // [B, S]
    const float* attn_W = (const float*)d_in[3];   // [E2+D, D]
    const float* attn_b = (const float*)d_in[4];   // [D]
    const float* v_W    = (const float*)d_in[5];   // [D]

    float* out = (float*)d_out;
    float* ctx = out;            // context [B, E2]
    float* wts = out + BB * EE;  // attn_weights [B, S]

    cudaFuncSetAttribute(scores_mma_kernel,
                         cudaFuncAttributeMaxDynamicSharedMemorySize, SMEM_SIZE);

    convert_enc<<<(BB * SS * EE) / (256 * 8), 256>>>(enc);
    transpose_we<<<dim3(EE / 32, DD / 32), dim3(32, 8)>>>(attn_W);
    hproj_kernel<<<dim3(DD / 128, BB), 128>>>(hidden, attn_W, attn_b);
    scores_mma_kernel<<<dim3(2, (BB * SS) / BM), 512, SMEM_SIZE>>>(v_W);
    softmax_kernel<<<BB, 256>>>(mask, wts);
    context_part_kernel<<<dim3(2, 8, BB), 128>>>(enc, wts);
    context_reduce_kernel<<<dim3(4, BB), 256>>>(ctx);
}

// round 9
// speedup vs baseline: 1.0498x; 1.0498x over previous
#include <cuda_runtime.h>
#include <cuda_fp16.h>
#include <math.h>
#include <stdint.h>

#define BB 64
#define SS 1024
#define EE 1024
#define DD 512

// ---------------- device scratch ----------------
__device__ float  g_hp[BB * DD];            // h_proj + bias  [B, D]
__device__ __half g_ench[(size_t)BB * SS * EE];  // enc in fp16 (134 MB)
__device__ __half g_WeTh[DD * EE];          // W_e^T in fp16 [D(n), E2(k)]
__device__ float  g_pscore[2 * BB * SS];    // per-n-tile score partials
__device__ float  g_ctx_part[8 * BB * EE];  // context partials

// ---------------- helpers ----------------
__device__ __forceinline__ uint32_t smem_u32(const void* p) {
    uint32_t a;
    asm("{ .reg .u64 t; cvta.to.shared.u64 t, %1; cvt.u32.u64 %0, t; }" : "=r"(a) : "l"(p));
    return a;
}
#define CP_ASYNC16(dst, src) \
    asm volatile("cp.async.cg.shared.global [%0], [%1], 16;" :: "r"(dst), "l"(src) : "memory")
#define CP_COMMIT() asm volatile("cp.async.commit_group;" ::: "memory")
#define CP_WAIT3()  asm volatile("cp.async.wait_group 3;" ::: "memory")
#define CP_WAIT0()  asm volatile("cp.async.wait_group 0;" ::: "memory")

__device__ __forceinline__ uint32_t pack_half2(float lo, float hi) {
    uint32_t r;
    asm("cvt.rn.f16x2.f32 %0, %1, %2;" : "=r"(r) : "f"(hi), "f"(lo));
    return r;
}

__device__ __forceinline__ void mma_f16(float c[4], uint32_t a0, uint32_t a1,
                                        uint32_t a2, uint32_t a3, uint32_t b0,
                                        uint32_t b1) {
    asm volatile(
        "mma.sync.aligned.m16n8k16.row.col.f32.f16.f16.f32 "
        "{%0,%1,%2,%3}, {%4,%5,%6,%7}, {%8,%9}, {%0,%1,%2,%3};"
        : "+f"(c[0]), "+f"(c[1]), "+f"(c[2]), "+f"(c[3])
        : "r"(a0), "r"(a1), "r"(a2), "r"(a3), "r"(b0), "r"(b1));
}

// ---------------- tiling ----------------
#define BM 128
#define BN 256
#define BK 32
#define NCHUNK (EE / BK)        // 32
#define NSLOT 5                 // smem slots; prefetch depth 4
#define RSB 80                  // row stride BYTES (64 data + 16 pad)
#define A_SZB (BM * RSB)        // 10240
#define B_SZB (BN * RSB)        // 20480
#define STAGE_B (A_SZB + B_SZB) // 30720
#define OFF_SHP (NSLOT * STAGE_B)             // 153600: hp tile (256 floats)
#define OFF_SV  (OFF_SHP + BN * 4)            // v tile (256 floats)
#define OFF_RED 0                             // red[128][17] aliases slot 0 (dead)
#define SMEM_SIZE (OFF_SV + BN * 4)           // 155648 B

// ---------------------------------------------------------------------------
// convert enc f32 -> fp16. grid 32768 x 256 thr, 8 elems/thread.
// ---------------------------------------------------------------------------
__global__ void __launch_bounds__(256) convert_enc(const float* __restrict__ enc) {
    size_t base = ((size_t)blockIdx.x * 256 + threadIdx.x) * 8;
    float4 v0 = *(const float4*)(enc + base);
    float4 v1 = *(const float4*)(enc + base + 4);
    uint4 o;
    o.x = pack_half2(v0.x, v0.y);
    o.y = pack_half2(v0.z, v0.w);
    o.z = pack_half2(v1.x, v1.y);
    o.w = pack_half2(v1.z, v1.w);
    *(uint4*)(&g_ench[base]) = o;
}

// ---------------------------------------------------------------------------
// transpose W_e [E2, D] -> g_WeTh [D, E2] fp16 (rn)
// ---------------------------------------------------------------------------
__global__ void transpose_we(const float* __restrict__ attn_W) {
    __shared__ float t[32][33];
    int k0 = blockIdx.x * 32, d0 = blockIdx.y * 32;
    for (int i = threadIdx.y; i < 32; i += 8)
        t[i][threadIdx.x] = attn_W[(size_t)(DD + k0 + i) * DD + d0 + threadIdx.x];
    __syncthreads();
    for (int i = threadIdx.y; i < 32; i += 8)
        g_WeTh[(size_t)(d0 + i) * EE + k0 + threadIdx.x] = __float2half_rn(t[threadIdx.x][i]);
}

// ---------------------------------------------------------------------------
// hp[b,d] = attn_b[d] + hidden[b,:] @ attn_W[:D, d]   (exact fp32)
// ---------------------------------------------------------------------------
__global__ void hproj_kernel(const float* __restrict__ hidden,
                             const float* __restrict__ attn_W,
                             const float* __restrict__ attn_b) {
    __shared__ float hrow[DD];
    int b = blockIdx.y;
    int d = blockIdx.x * 128 + threadIdx.x;
    for (int i = threadIdx.x; i < DD; i += 128) hrow[i] = hidden[b * DD + i];
    __syncthreads();
    float acc = attn_b[d];
#pragma unroll 8
    for (int k = 0; k < DD; k++) acc += hrow[k] * attn_W[k * DD + d];
    g_hp[b * DD + d] = acc;
}

// ---------------------------------------------------------------------------
// scores: fp16 m16n8k16 GEMM (128x256 tile, K=1024).
// 5-slot cp.async pipeline, depth 4, ONE __syncthreads per chunk:
//   iter c: wait_group 3 (chunk c landed) -> sync -> issue chunk c+4 into
//   slot (c+4)%5 (that slot was computed at iter c-1; barrier protects) ->
//   compute chunk c. One (possibly empty) commit per iter keeps the
//   wait_group count uniform.
// 256 threads (8 warps, each 64x64), k-slot permutation as before.
// grid (2 n-tiles, 512 row-tiles).
// ---------------------------------------------------------------------------
__global__ void __launch_bounds__(256, 1)
scores_mma_kernel(const float* __restrict__ vW) {
    extern __shared__ char smem[];
    uint32_t sb = smem_u32(smem);
    int tid = threadIdx.x;
    int wid = tid >> 5, lid = tid & 31;
    int gid = lid >> 2, tig = lid & 3;
    int wm = wid >> 2, wn = wid & 3;       // warp grid 2(m) x 4(n)
    int nt = blockIdx.x;                   // n tile (0..1)
    int r0 = blockIdx.y * BM;              // global row
    int b = r0 / SS;
    int n0 = nt * BN;

    float* shp = (float*)(smem + OFF_SHP);
    float* sv  = (float*)(smem + OFF_SV);
    for (int i = tid; i < BN; i += 256) {
        shp[i] = g_hp[b * DD + n0 + i];
        sv[i]  = vW[n0 + i];
    }

    const __half* Abase = g_ench + (size_t)r0 * EE;
    const __half* Bbase = g_WeTh + (size_t)n0 * EE;

    auto load_chunk = [&](int c, int slot) {
        uint32_t sA = sb + slot * STAGE_B;
        uint32_t sB = sA + A_SZB;
#pragma unroll
        for (int i = 0; i < 2; i++) {                 // A: 512 16B chunks
            int idx = tid + i * 256;
            int row = idx >> 2, ch = idx & 3;
            CP_ASYNC16(sA + row * RSB + ch * 16,
                       Abase + (size_t)row * EE + c * BK + ch * 8);
        }
#pragma unroll
        for (int i = 0; i < 4; i++) {                 // B: 1024 16B chunks
            int idx = tid + i * 256;
            int row = idx >> 2, ch = idx & 3;
            CP_ASYNC16(sB + row * RSB + ch * 16,
                       Bbase + (size_t)row * EE + c * BK + ch * 8);
        }
        CP_COMMIT();
    };

    float acc[4][8][4];
#pragma unroll
    for (int mf = 0; mf < 4; mf++)
#pragma unroll
        for (int nf = 0; nf < 8; nf++)
#pragma unroll
            for (int q = 0; q < 4; q++) acc[mf][nf][q] = 0.f;

    load_chunk(0, 0);
    load_chunk(1, 1);
    load_chunk(2, 2);
    load_chunk(3, 3);

    for (int c = 0; c < NCHUNK; c++) {
        int slot = c % NSLOT;
        CP_WAIT3();
        __syncthreads();
        // issue next load first (slot (c+4)%NSLOT is free; barrier above
        // guarantees every warp finished computing it at iter c-1)
        if (c + 4 < NCHUNK) load_chunk(c + 4, (c + 4) % NSLOT);
        else CP_COMMIT();   // empty group keeps wait_group 3 uniform

        const char* fA = smem + slot * STAGE_B;
        const char* fB = smem + slot * STAGE_B + A_SZB;

        uint4 alo[4], ahi[4], bv[8];   // 8 halves each: phys k = 8*tig..+7
#pragma unroll
        for (int mf = 0; mf < 4; mf++) {
            int m0 = wm * 64 + mf * 16 + gid;
            alo[mf] = *(const uint4*)(fA + m0 * RSB + tig * 16);
            ahi[mf] = *(const uint4*)(fA + (m0 + 8) * RSB + tig * 16);
        }
#pragma unroll
        for (int nf = 0; nf < 8; nf++) {
            int nr = wn * 64 + nf * 8 + gid;
            bv[nf] = *(const uint4*)(fB + nr * RSB + tig * 16);
        }
        // instr 0: half-pairs 0,1 (phys k 8t..8t+3)
#pragma unroll
        for (int mf = 0; mf < 4; mf++)
#pragma unroll
            for (int nf = 0; nf < 8; nf++)
                mma_f16(acc[mf][nf], alo[mf].x, ahi[mf].x, alo[mf].y, ahi[mf].y,
                        bv[nf].x, bv[nf].y);
        // instr 1: half-pairs 2,3 (phys k 8t+4..8t+7)
#pragma unroll
        for (int mf = 0; mf < 4; mf++)
#pragma unroll
            for (int nf = 0; nf < 8; nf++)
                mma_f16(acc[mf][nf], alo[mf].z, ahi[mf].z, alo[mf].w, ahi[mf].w,
                        bv[nf].z, bv[nf].w);
    }
    CP_WAIT0();
    __syncthreads();   // slots dead; red aliases slot 0

    // ---- epilogue: score partial = sum_n v[n] * tanh(acc + hp[n]) ----
    float* red = (float*)(smem + OFF_RED);  // [128][17]
#pragma unroll
    for (int mf = 0; mf < 4; mf++) {
#pragma unroll
        for (int half = 0; half < 2; half++) {
            int r = wm * 64 + mf * 16 + half * 8 + gid;
            float s = 0.f;
#pragma unroll
            for (int nf = 0; nf < 8; nf++) {
                int nl = wn * 64 + nf * 8 + tig * 2;
                float e0 = acc[mf][nf][half * 2 + 0] + shp[nl];
                float e1 = acc[mf][nf][half * 2 + 1] + shp[nl + 1];
                float t0, t1;
                asm("tanh.approx.f32 %0, %1;" : "=f"(t0) : "f"(e0));
                asm("tanh.approx.f32 %0, %1;" : "=f"(t1) : "f"(e1));
                s = fmaf(sv[nl], t0, s);
                s = fmaf(sv[nl + 1], t1, s);
            }
            red[r * 17 + wn * 4 + tig] = s;
        }
    }
    __syncthreads();
    if (tid < BM) {
        float s = 0.f;
#pragma unroll
        for (int t = 0; t < 16; t++) s += red[tid * 17 + t];
        g_pscore[nt * (BB * SS) + r0 + tid] = s;
    }
}

// ---------------------------------------------------------------------------
// softmax: combine 2 partials, mask, softmax over S. grid(64), 256 threads.
// ---------------------------------------------------------------------------
__global__ void softmax_kernel(const int* __restrict__ mask,
                               float* __restrict__ wout) {
    int b = blockIdx.x;
    __shared__ float sc[SS];
    __shared__ float redbuf[256];
    int tid = threadIdx.x;

    float lmax = -3.402823466e38f;
    for (int s = tid; s < SS; s += 256) {
        int idx = b * SS + s;
        float v = g_pscore[idx] + g_pscore[BB * SS + idx];
        if (mask[idx] == 0) v = -3.402823466e38f;
        sc[s] = v;
        lmax = fmaxf(lmax, v);
    }
    redbuf[tid] = lmax;
    __syncthreads();
    for (int o = 128; o > 0; o >>= 1) {
        if (tid < o) redbuf[tid] = fmaxf(redbuf[tid], redbuf[tid + o]);
        __syncthreads();
    }
    float m = redbuf[0];
    __syncthreads();

    float lsum = 0.f;
    for (int s = tid; s < SS; s += 256) {
        float e = expf(sc[s] - m);
        sc[s] = e;
        lsum += e;
    }
    redbuf[tid] = lsum;
    __syncthreads();
    for (int o = 128; o > 0; o >>= 1) {
        if (tid < o) redbuf[tid] += redbuf[tid + o];
        __syncthreads();
    }
    float inv = 1.f / redbuf[0];
    for (int s = tid; s < SS; s += 256) wout[b * SS + s] = sc[s] * inv;
}

// ---------------------------------------------------------------------------
// context partials from fp16 enc: grid (8, 64), 128 threads; 8 halves/thread.
// ---------------------------------------------------------------------------
__global__ void __launch_bounds__(128) context_part_kernel(
    const float* __restrict__ w) {
    __shared__ float ws[128];
    int sy = blockIdx.x, b = blockIdx.y;
    int e0 = threadIdx.x * 8;
    ws[threadIdx.x] = w[b * SS + sy * 128 + threadIdx.x];
    __syncthreads();
    const __half* base = g_ench + ((size_t)b * SS + sy * 128) * EE + e0;
    float acc[8];
#pragma unroll
    for (int j = 0; j < 8; j++) acc[j] = 0.f;
#pragma unroll 4
    for (int r = 0; r < 128; r++) {
        uint4 v = *(const uint4*)(base + (size_t)r * EE);
        float c = ws[r];
        const uint32_t* p = (const uint32_t*)&v;
#pragma unroll
        for (int q = 0; q < 4; q++) {
            float2 f = __half22float2(*(const __half2*)&p[q]);
            acc[q * 2 + 0] = fmaf(c, f.x, acc[q * 2 + 0]);
            acc[q * 2 + 1] = fmaf(c, f.y, acc[q * 2 + 1]);
        }
    }
    float* dst = &g_ctx_part[((size_t)sy * BB + b) * EE + e0];
    *(float4*)dst = make_float4(acc[0], acc[1], acc[2], acc[3]);
    *(float4*)(dst + 4) = make_float4(acc[4], acc[5], acc[6], acc[7]);
}

__global__ void context_reduce_kernel(float* __restrict__ ctx) {
    int b = blockIdx.y;
    int e = blockIdx.x * 256 + threadIdx.x;
    float s = 0.f;
#pragma unroll
    for (int sy = 0; sy < 8; sy++) s += g_ctx_part[((size_t)sy * BB + b) * EE + e];
    ctx[b * EE + e] = s;
}

// ---------------------------------------------------------------------------
extern "C" void kernel_launch(void* const* d_in, const int* in_sizes, int n_in,
                              void* d_out, int out_size) {
    const float* hidden = (const float*)d_in[0];   // [B, D]
    const float* enc    = (const float*)d_in[1];   // [B, S, E2]
    const int*   mask   = (const int*)d_in[2];     // [B, S]
    const float* attn_W = (const float*)d_in[3];   // [E2+D, D]
    const float* attn_b = (const float*)d_in[4];   // [D]
    const float* v_W    = (const float*)d_in[5];   // [D]

    float* out = (float*)d_out;
    float* ctx = out;            // context [B, E2]
    float* wts = out + BB * EE;  // attn_weights [B, S]

    cudaFuncSetAttribute(scores_mma_kernel,
                         cudaFuncAttributeMaxDynamicSharedMemorySize, SMEM_SIZE);

    convert_enc<<<(BB * SS * EE) / (256 * 8), 256>>>(enc);
    transpose_we<<<dim3(EE / 32, DD / 32), dim3(32, 8)>>>(attn_W);
    hproj_kernel<<<dim3(DD / 128, BB), 128>>>(hidden, attn_W, attn_b);
    scores_mma_kernel<<<dim3(2, (BB * SS) / BM), 256, SMEM_SIZE>>>(v_W);
    softmax_kernel<<<BB, 256>>>(mask, wts);
    context_part_kernel<<<dim3(8, BB), 128>>>(wts);
    context_reduce_kernel<<<dim3(4, BB), 256>>>(ctx);
}

// round 10
// speedup vs baseline: 1.1573x; 1.1024x over previous
#include <cuda_runtime.h>
#include <cuda_fp16.h>
#include <math.h>
#include <stdint.h>

#define BB 64
#define SS 1024
#define EE 1024
#define DD 512

// ---------------- device scratch ----------------
__device__ float  g_hp[BB * DD];            // h_proj + bias  [B, D]
__device__ __half g_ench[(size_t)BB * SS * EE];  // enc in fp16 (134 MB)
__device__ __half g_WeTh[DD * EE];          // W_e^T in fp16 [D(n), E2(k)]
__device__ float  g_pscore[2 * BB * SS];    // per-n-tile score partials
__device__ float  g_ctx_part[8 * BB * EE];  // context partials

// ---------------- helpers ----------------
__device__ __forceinline__ uint32_t smem_u32(const void* p) {
    uint32_t a;
    asm("{ .reg .u64 t; cvta.to.shared.u64 t, %1; cvt.u32.u64 %0, t; }" : "=r"(a) : "l"(p));
    return a;
}
#define CP_ASYNC16(dst, src) \
    asm volatile("cp.async.cg.shared.global [%0], [%1], 16;" :: "r"(dst), "l"(src) : "memory")
#define CP_COMMIT() asm volatile("cp.async.commit_group;" ::: "memory")
#define CP_WAIT3()  asm volatile("cp.async.wait_group 3;" ::: "memory")
#define CP_WAIT0()  asm volatile("cp.async.wait_group 0;" ::: "memory")

__device__ __forceinline__ uint32_t pack_half2(float lo, float hi) {
    uint32_t r;
    asm("cvt.rn.f16x2.f32 %0, %1, %2;" : "=r"(r) : "f"(hi), "f"(lo));
    return r;
}

__device__ __forceinline__ void mma_f16(float c[4], uint32_t a0, uint32_t a1,
                                        uint32_t a2, uint32_t a3, uint32_t b0,
                                        uint32_t b1) {
    asm volatile(
        "mma.sync.aligned.m16n8k16.row.col.f32.f16.f16.f32 "
        "{%0,%1,%2,%3}, {%4,%5,%6,%7}, {%8,%9}, {%0,%1,%2,%3};"
        : "+f"(c[0]), "+f"(c[1]), "+f"(c[2]), "+f"(c[3])
        : "r"(a0), "r"(a1), "r"(a2), "r"(a3), "r"(b0), "r"(b1));
}

// ---------------- tiling ----------------
#define BM 128
#define BN 256
#define BK 32
#define NCHUNK (EE / BK)        // 32
#define NSTAGE 4
#define RSB 80                  // row stride BYTES (64 data + 16 pad)
#define A_SZB (BM * RSB)        // 10240
#define B_SZB (BN * RSB)        // 20480
#define STAGE_B (A_SZB + B_SZB) // 30720
#define OFF_SHP (NSTAGE * STAGE_B)            // 122880: hp tile (256 floats)
#define OFF_SV  (OFF_SHP + BN * 4)            // v tile (256 floats)
#define OFF_RED 0                             // red[128][17] aliases stage 0 (dead)
#define SMEM_SIZE (OFF_SV + BN * 4)           // 124928 B

// ---------------------------------------------------------------------------
// convert enc f32 -> fp16. grid 32768 x 256 thr, 8 elems/thread.
// ---------------------------------------------------------------------------
__global__ void __launch_bounds__(256) convert_enc(const float* __restrict__ enc) {
    size_t base = ((size_t)blockIdx.x * 256 + threadIdx.x) * 8;
    float4 v0 = *(const float4*)(enc + base);
    float4 v1 = *(const float4*)(enc + base + 4);
    uint4 o;
    o.x = pack_half2(v0.x, v0.y);
    o.y = pack_half2(v0.z, v0.w);
    o.z = pack_half2(v1.x, v1.y);
    o.w = pack_half2(v1.z, v1.w);
    *(uint4*)(&g_ench[base]) = o;
}

// ---------------------------------------------------------------------------
// transpose W_e [E2, D] -> g_WeTh [D, E2] fp16 (rn)
// ---------------------------------------------------------------------------
__global__ void transpose_we(const float* __restrict__ attn_W) {
    __shared__ float t[32][33];
    int k0 = blockIdx.x * 32, d0 = blockIdx.y * 32;
    for (int i = threadIdx.y; i < 32; i += 8)
        t[i][threadIdx.x] = attn_W[(size_t)(DD + k0 + i) * DD + d0 + threadIdx.x];
    __syncthreads();
    for (int i = threadIdx.y; i < 32; i += 8)
        g_WeTh[(size_t)(d0 + i) * EE + k0 + threadIdx.x] = __float2half_rn(t[threadIdx.x][i]);
}

// ---------------------------------------------------------------------------
// hp[b,d] = attn_b[d] + hidden[b,:] @ attn_W[:D, d]   (exact fp32)
// ---------------------------------------------------------------------------
__global__ void hproj_kernel(const float* __restrict__ hidden,
                             const float* __restrict__ attn_W,
                             const float* __restrict__ attn_b) {
    __shared__ float hrow[DD];
    int b = blockIdx.y;
    int d = blockIdx.x * 128 + threadIdx.x;
    for (int i = threadIdx.x; i < DD; i += 128) hrow[i] = hidden[b * DD + i];
    __syncthreads();
    float acc = attn_b[d];
#pragma unroll 8
    for (int k = 0; k < DD; k++) acc += hrow[k] * attn_W[k * DD + d];
    g_hp[b * DD + d] = acc;
}

// ---------------------------------------------------------------------------
// scores: fp16 m16n8k16 GEMM (128x256 tile, K=1024), 4-stage cp.async.
// CUTLASS-style ordering per chunk:
//   wait3 -> sync -> LDS fragments (slot c&3) -> sync -> issue cp.async for
//   chunk c+4 into the SAME slot (now free) -> MMA block.
// Loads are in flight during the whole MMA block of the current chunk.
// 256 threads (8 warps, each 64x64), k-slot permutation. grid (2, 512).
// ---------------------------------------------------------------------------
__global__ void __launch_bounds__(256, 1)
scores_mma_kernel(const float* __restrict__ vW) {
    extern __shared__ char smem[];
    uint32_t sb = smem_u32(smem);
    int tid = threadIdx.x;
    int wid = tid >> 5, lid = tid & 31;
    int gid = lid >> 2, tig = lid & 3;
    int wm = wid >> 2, wn = wid & 3;       // warp grid 2(m) x 4(n)
    int nt = blockIdx.x;                   // n tile (0..1)
    int r0 = blockIdx.y * BM;              // global row
    int b = r0 / SS;
    int n0 = nt * BN;

    float* shp = (float*)(smem + OFF_SHP);
    float* sv  = (float*)(smem + OFF_SV);
    for (int i = tid; i < BN; i += 256) {
        shp[i] = g_hp[b * DD + n0 + i];
        sv[i]  = vW[n0 + i];
    }

    const __half* Abase = g_ench + (size_t)r0 * EE;
    const __half* Bbase = g_WeTh + (size_t)n0 * EE;

    auto load_chunk = [&](int c, int slot) {
        uint32_t sA = sb + slot * STAGE_B;
        uint32_t sB = sA + A_SZB;
#pragma unroll
        for (int i = 0; i < 2; i++) {                 // A: 512 16B chunks
            int idx = tid + i * 256;
            int row = idx >> 2, ch = idx & 3;
            CP_ASYNC16(sA + row * RSB + ch * 16,
                       Abase + (size_t)row * EE + c * BK + ch * 8);
        }
#pragma unroll
        for (int i = 0; i < 4; i++) {                 // B: 1024 16B chunks
            int idx = tid + i * 256;
            int row = idx >> 2, ch = idx & 3;
            CP_ASYNC16(sB + row * RSB + ch * 16,
                       Bbase + (size_t)row * EE + c * BK + ch * 8);
        }
        CP_COMMIT();
    };

    float acc[4][8][4];
#pragma unroll
    for (int mf = 0; mf < 4; mf++)
#pragma unroll
        for (int nf = 0; nf < 8; nf++)
#pragma unroll
            for (int q = 0; q < 4; q++) acc[mf][nf][q] = 0.f;

    load_chunk(0, 0);
    load_chunk(1, 1);
    load_chunk(2, 2);
    load_chunk(3, 3);

#pragma unroll 4
    for (int c = 0; c < NCHUNK; c++) {
        int slot = c & 3;
        CP_WAIT3();
        __syncthreads();
        const char* fA = smem + slot * STAGE_B;
        const char* fB = smem + slot * STAGE_B + A_SZB;

        uint4 alo[4], ahi[4], bv[8];   // 8 halves each: phys k = 8*tig..+7
#pragma unroll
        for (int mf = 0; mf < 4; mf++) {
            int m0 = wm * 64 + mf * 16 + gid;
            alo[mf] = *(const uint4*)(fA + m0 * RSB + tig * 16);
            ahi[mf] = *(const uint4*)(fA + (m0 + 8) * RSB + tig * 16);
        }
#pragma unroll
        for (int nf = 0; nf < 8; nf++) {
            int nr = wn * 64 + nf * 8 + gid;
            bv[nf] = *(const uint4*)(fB + nr * RSB + tig * 16);
        }
        // fragments for this slot are (being) read into regs; barrier, then
        // refill the same slot while the MMA block runs
        __syncthreads();
        if (c + 4 < NCHUNK) load_chunk(c + 4, slot);

        // instr 0: half-pairs 0,1 (phys k 8t..8t+3)
#pragma unroll
        for (int mf = 0; mf < 4; mf++)
#pragma unroll
            for (int nf = 0; nf < 8; nf++)
                mma_f16(acc[mf][nf], alo[mf].x, ahi[mf].x, alo[mf].y, ahi[mf].y,
                        bv[nf].x, bv[nf].y);
        // instr 1: half-pairs 2,3 (phys k 8t+4..8t+7)
#pragma unroll
        for (int mf = 0; mf < 4; mf++)
#pragma unroll
            for (int nf = 0; nf < 8; nf++)
                mma_f16(acc[mf][nf], alo[mf].z, ahi[mf].z, alo[mf].w, ahi[mf].w,
                        bv[nf].z, bv[nf].w);
    }
    CP_WAIT0();
    __syncthreads();   // stages dead; red aliases stage 0

    // ---- epilogue: score partial = sum_n v[n] * tanh(acc + hp[n]) ----
    float* red = (float*)(smem + OFF_RED);  // [128][17]
#pragma unroll
    for (int mf = 0; mf < 4; mf++) {
#pragma unroll
        for (int half = 0; half < 2; half++) {
            int r = wm * 64 + mf * 16 + half * 8 + gid;
            float s = 0.f;
#pragma unroll
            for (int nf = 0; nf < 8; nf++) {
                int nl = wn * 64 + nf * 8 + tig * 2;
                float e0 = acc[mf][nf][half * 2 + 0] + shp[nl];
                float e1 = acc[mf][nf][half * 2 + 1] + shp[nl + 1];
                float t0, t1;
                asm("tanh.approx.f32 %0, %1;" : "=f"(t0) : "f"(e0));
                asm("tanh.approx.f32 %0, %1;" : "=f"(t1) : "f"(e1));
                s = fmaf(sv[nl], t0, s);
                s = fmaf(sv[nl + 1], t1, s);
            }
            red[r * 17 + wn * 4 + tig] = s;
        }
    }
    __syncthreads();
    if (tid < BM) {
        float s = 0.f;
#pragma unroll
        for (int t = 0; t < 16; t++) s += red[tid * 17 + t];
        g_pscore[nt * (BB * SS) + r0 + tid] = s;
    }
}

// ---------------------------------------------------------------------------
// softmax: combine 2 partials, mask, softmax over S. grid(64), 256 threads.
// ---------------------------------------------------------------------------
__global__ void softmax_kernel(const int* __restrict__ mask,
                               float* __restrict__ wout) {
    int b = blockIdx.x;
    __shared__ float sc[SS];
    __shared__ float redbuf[256];
    int tid = threadIdx.x;

    float lmax = -3.402823466e38f;
    for (int s = tid; s < SS; s += 256) {
        int idx = b * SS + s;
        float v = g_pscore[idx] + g_pscore[BB * SS + idx];
        if (mask[idx] == 0) v = -3.402823466e38f;
        sc[s] = v;
        lmax = fmaxf(lmax, v);
    }
    redbuf[tid] = lmax;
    __syncthreads();
    for (int o = 128; o > 0; o >>= 1) {
        if (tid < o) redbuf[tid] = fmaxf(redbuf[tid], redbuf[tid + o]);
        __syncthreads();
    }
    float m = redbuf[0];
    __syncthreads();

    float lsum = 0.f;
    for (int s = tid; s < SS; s += 256) {
        float e = expf(sc[s] - m);
        sc[s] = e;
        lsum += e;
    }
    redbuf[tid] = lsum;
    __syncthreads();
    for (int o = 128; o > 0; o >>= 1) {
        if (tid < o) redbuf[tid] += redbuf[tid + o];
        __syncthreads();
    }
    float inv = 1.f / redbuf[0];
    for (int s = tid; s < SS; s += 256) wout[b * SS + s] = sc[s] * inv;
}

// ---------------------------------------------------------------------------
// context partials from fp16 enc: grid (8, 64), 128 threads; 8 halves/thread.
// ---------------------------------------------------------------------------
__global__ void __launch_bounds__(128) context_part_kernel(
    const float* __restrict__ w) {
    __shared__ float ws[128];
    int sy = blockIdx.x, b = blockIdx.y;
    int e0 = threadIdx.x * 8;
    ws[threadIdx.x] = w[b * SS + sy * 128 + threadIdx.x];
    __syncthreads();
    const __half* base = g_ench + ((size_t)b * SS + sy * 128) * EE + e0;
    float acc[8];
#pragma unroll
    for (int j = 0; j < 8; j++) acc[j] = 0.f;
#pragma unroll 4
    for (int r = 0; r < 128; r++) {
        uint4 v = *(const uint4*)(base + (size_t)r * EE);
        float c = ws[r];
        const uint32_t* p = (const uint32_t*)&v;
#pragma unroll
        for (int q = 0; q < 4; q++) {
            float2 f = __half22float2(*(const __half2*)&p[q]);
            acc[q * 2 + 0] = fmaf(c, f.x, acc[q * 2 + 0]);
            acc[q * 2 + 1] = fmaf(c, f.y, acc[q * 2 + 1]);
        }
    }
    float* dst = &g_ctx_part[((size_t)sy * BB + b) * EE + e0];
    *(float4*)dst = make_float4(acc[0], acc[1], acc[2], acc[3]);
    *(float4*)(dst + 4) = make_float4(acc[4], acc[5], acc[6], acc[7]);
}

__global__ void context_reduce_kernel(float* __restrict__ ctx) {
    int b = blockIdx.y;
    int e = blockIdx.x * 256 + threadIdx.x;
    float s = 0.f;
#pragma unroll
    for (int sy = 0; sy < 8; sy++) s += g_ctx_part[((size_t)sy * BB + b) * EE + e];
    ctx[b * EE + e] = s;
}

// ---------------------------------------------------------------------------
extern "C" void kernel_launch(void* const* d_in, const int* in_sizes, int n_in,
                              void* d_out, int out_size) {
    const float* hidden = (const float*)d_in[0];   // [B, D]
    const float* enc    = (const float*)d_in[1];   // [B, S, E2]
    const int*   mask   = (const int*)d_in[2];     // [B, S]
    const float* attn_W = (const float*)d_in[3];   // [E2+D, D]
    const float* attn_b = (const float*)d_in[4];   // [D]
    const float* v_W    = (const float*)d_in[5];   // [D]

    float* out = (float*)d_out;
    float* ctx = out;            // context [B, E2]
    float* wts = out + BB * EE;  // attn_weights [B, S]

    cudaFuncSetAttribute(scores_mma_kernel,
                         cudaFuncAttributeMaxDynamicSharedMemorySize, SMEM_SIZE);

    convert_enc<<<(BB * SS * EE) / (256 * 8), 256>>>(enc);
    transpose_we<<<dim3(EE / 32, DD / 32), dim3(32, 8)>>>(attn_W);
    hproj_kernel<<<dim3(DD / 128, BB), 128>>>(hidden, attn_W, attn_b);
    scores_mma_kernel<<<dim3(2, (BB * SS) / BM), 256, SMEM_SIZE>>>(v_W);
    softmax_kernel<<<BB, 256>>>(mask, wts);
    context_part_kernel<<<dim3(8, BB), 128>>>(wts);
    context_reduce_kernel<<<dim3(4, BB), 256>>>(ctx);
}

// round 11
// speedup vs baseline: 1.3129x; 1.1344x over previous
#include <cuda_runtime.h>
#include <cuda.h>
#include <cuda_fp16.h>
#include <math.h>
#include <stdint.h>

#define BB 64
#define SS 1024
#define EE 1024
#define DD 512

// ---------------- device scratch ----------------
__device__ float  g_hp[BB * DD];            // h_proj + bias  [B, D]
__device__ __half g_ench[(size_t)BB * SS * EE];  // enc in fp16 (134 MB)
__device__ __half g_WeTh[DD * EE];          // W_e^T in fp16 [D(n), E2(k)]
__device__ float  g_pscore[2 * BB * SS];    // per-n-tile score partials
__device__ float  g_ctx_part[8 * BB * EE];  // context partials

// ---------------- helpers ----------------
__device__ __forceinline__ uint32_t smem_u32(const void* p) {
    uint32_t a;
    asm("{ .reg .u64 t; cvta.to.shared.u64 t, %1; cvt.u32.u64 %0, t; }" : "=r"(a) : "l"(p));
    return a;
}

#define MBARRIER_INIT(addr, cnt) \
    asm volatile("mbarrier.init.shared.b64 [%0], %1;" :: "r"(addr), "r"(cnt) : "memory")
#define MBARRIER_INVAL(addr) \
    asm volatile("mbarrier.inval.shared.b64 [%0];" :: "r"(addr) : "memory")
#define MBARRIER_EXPECT_TX(addr, bytes) \
    asm volatile("mbarrier.arrive.expect_tx.shared.b64 _, [%0], %1;" :: "r"(addr), "r"(bytes) : "memory")
#define MBARRIER_WAIT_PARITY(addr, parity) do {                                     \
    uint32_t _m = (addr), _p = (parity);                                            \
    asm volatile(                                                                   \
        "{\n\t.reg .pred P1;\n\t"                                                   \
        "WL_%=:\n\t"                                                                \
        "mbarrier.try_wait.parity.acquire.cta.shared::cta.b64 P1, [%0], %1, 0x989680;\n\t" \
        "@P1 bra.uni WD_%=;\n\t"                                                    \
        "bra.uni WL_%=;\n\t"                                                        \
        "WD_%=:\n\t}"                                                               \
        :: "r"(_m), "r"(_p) : "memory");                                            \
} while (0)
#define TMA_LOAD_2D(smem, map, cx, cy, mbar)                                        \
    asm volatile(                                                                   \
        "cp.async.bulk.tensor.2d.shared::cta.global.tile.mbarrier::complete_tx::bytes " \
        "[%0], [%1, {%2, %3}], [%4];"                                               \
        :: "r"(smem), "l"(map), "r"(cx), "r"(cy), "r"(mbar) : "memory")

__device__ __forceinline__ uint32_t pack_half2(float lo, float hi) {
    uint32_t r;
    asm("cvt.rn.f16x2.f32 %0, %1, %2;" : "=r"(r) : "f"(hi), "f"(lo));
    return r;
}

__device__ __forceinline__ void mma_f16(float c[4], uint32_t a0, uint32_t a1,
                                        uint32_t a2, uint32_t a3, uint32_t b0,
                                        uint32_t b1) {
    asm volatile(
        "mma.sync.aligned.m16n8k16.row.col.f32.f16.f16.f32 "
        "{%0,%1,%2,%3}, {%4,%5,%6,%7}, {%8,%9}, {%0,%1,%2,%3};"
        : "+f"(c[0]), "+f"(c[1]), "+f"(c[2]), "+f"(c[3])
        : "r"(a0), "r"(a1), "r"(a2), "r"(a3), "r"(b0), "r"(b1));
}

// ---------------- tiling ----------------
#define BM 128
#define BN 256
#define BK 32
#define NCHUNK (EE / BK)        // 32
#define A_SZB (BM * 64)         // 8192  (64B rows, TMA SW64, no pad)
#define B_SZB (BN * 64)         // 16384
#define STAGE_B (A_SZB + B_SZB) // 24576
#define OFF_SLOT 1024
#define OFF_SHP (OFF_SLOT + 4 * STAGE_B)      // 99328
#define OFF_SV  (OFF_SHP + BN * 4)
#define OFF_RED OFF_SLOT                      // red[128][17] aliases slot 0 (dead)
#define SMEM_SIZE (OFF_SV + BN * 4)           // 101376 B

// ---------------------------------------------------------------------------
// convert enc f32 -> fp16. grid 32768 x 256 thr, 8 elems/thread.
// ---------------------------------------------------------------------------
__global__ void __launch_bounds__(256) convert_enc(const float* __restrict__ enc) {
    size_t base = ((size_t)blockIdx.x * 256 + threadIdx.x) * 8;
    float4 v0 = *(const float4*)(enc + base);
    float4 v1 = *(const float4*)(enc + base + 4);
    uint4 o;
    o.x = pack_half2(v0.x, v0.y);
    o.y = pack_half2(v0.z, v0.w);
    o.z = pack_half2(v1.x, v1.y);
    o.w = pack_half2(v1.z, v1.w);
    *(uint4*)(&g_ench[base]) = o;
}

// ---------------------------------------------------------------------------
// transpose W_e [E2, D] -> g_WeTh [D, E2] fp16 (rn)
// ---------------------------------------------------------------------------
__global__ void transpose_we(const float* __restrict__ attn_W) {
    __shared__ float t[32][33];
    int k0 = blockIdx.x * 32, d0 = blockIdx.y * 32;
    for (int i = threadIdx.y; i < 32; i += 8)
        t[i][threadIdx.x] = attn_W[(size_t)(DD + k0 + i) * DD + d0 + threadIdx.x];
    __syncthreads();
    for (int i = threadIdx.y; i < 32; i += 8)
        g_WeTh[(size_t)(d0 + i) * EE + k0 + threadIdx.x] = __float2half_rn(t[threadIdx.x][i]);
}

// ---------------------------------------------------------------------------
// hp[b,d] = attn_b[d] + hidden[b,:] @ attn_W[:D, d]   (exact fp32)
// ---------------------------------------------------------------------------
__global__ void hproj_kernel(const float* __restrict__ hidden,
                             const float* __restrict__ attn_W,
                             const float* __restrict__ attn_b) {
    __shared__ float hrow[DD];
    int b = blockIdx.y;
    int d = blockIdx.x * 128 + threadIdx.x;
    for (int i = threadIdx.x; i < DD; i += 128) hrow[i] = hidden[b * DD + i];
    __syncthreads();
    float acc = attn_b[d];
#pragma unroll 8
    for (int k = 0; k < DD; k++) acc += hrow[k] * attn_W[k * DD + d];
    g_hp[b * DD + d] = acc;
}

// ---------------------------------------------------------------------------
// scores: fp16 m16n8k16 GEMM (128x256 tile, K=1024), TMA-fed 4-slot pipeline.
// Per chunk: mbarrier wait -> LDS fragments -> __syncthreads -> thread 0
// issues TMA for chunk c+4 into the now-free slot -> MMA block.
// TMA SW64 swizzle: smem 16B-unit c' = c ^ ((row>>1)&3). All fragment rows
// are ≡ gid (mod 8), so the per-lane swizzled offset (tig ^ ((gid>>1)&3))*16
// is loop-invariant. 256 threads (8 warps, 64x64 each). grid (2, 512).
// ---------------------------------------------------------------------------
__global__ void __launch_bounds__(256, 1)
scores_mma_kernel(const __grid_constant__ CUtensorMap tmA,
                  const __grid_constant__ CUtensorMap tmB,
                  const float* __restrict__ vW) {
    extern __shared__ char smem[];
    uint32_t sb = smem_u32(smem);
    int tid = threadIdx.x;
    int wid = tid >> 5, lid = tid & 31;
    int gid = lid >> 2, tig = lid & 3;
    int wm = wid >> 2, wn = wid & 3;       // warp grid 2(m) x 4(n)
    int nt = blockIdx.x;                   // n tile (0..1)
    int r0 = blockIdx.y * BM;              // global row
    int b = r0 / SS;
    int n0 = nt * BN;
    int swt = (tig ^ ((gid >> 1) & 3)) * 16;   // loop-invariant swizzled 16B offset

    float* shp = (float*)(smem + OFF_SHP);
    float* sv  = (float*)(smem + OFF_SV);
    for (int i = tid; i < BN; i += 256) {
        shp[i] = g_hp[b * DD + n0 + i];
        sv[i]  = vW[n0 + i];
    }
    if (tid == 0) {
#pragma unroll
        for (int p = 0; p < 4; p++) MBARRIER_INIT(sb + 16 + p * 8, 1);
    }
    __syncthreads();

    if (tid == 0) {
#pragma unroll
        for (int p = 0; p < 4; p++) {
            uint32_t slot = sb + OFF_SLOT + p * STAGE_B;
            MBARRIER_EXPECT_TX(sb + 16 + p * 8, (uint32_t)STAGE_B);
            TMA_LOAD_2D(slot, &tmA, p * BK, r0, sb + 16 + p * 8);
            TMA_LOAD_2D(slot + A_SZB, &tmB, p * BK, n0, sb + 16 + p * 8);
        }
    }

    float acc[4][8][4];
#pragma unroll
    for (int mf = 0; mf < 4; mf++)
#pragma unroll
        for (int nf = 0; nf < 8; nf++)
#pragma unroll
            for (int q = 0; q < 4; q++) acc[mf][nf][q] = 0.f;

#pragma unroll 4
    for (int c = 0; c < NCHUNK; c++) {
        int slot = c & 3;
        uint32_t mb = sb + 16 + slot * 8;
        MBARRIER_WAIT_PARITY(mb, (uint32_t)((c >> 2) & 1));

        const char* fA = smem + OFF_SLOT + slot * STAGE_B;
        const char* fB = fA + A_SZB;

        uint4 alo[4], ahi[4], bv[8];   // 8 halves each: phys k = 8*tig..+7
#pragma unroll
        for (int mf = 0; mf < 4; mf++) {
            int m0 = wm * 64 + mf * 16 + gid;
            alo[mf] = *(const uint4*)(fA + m0 * 64 + swt);
            ahi[mf] = *(const uint4*)(fA + (m0 + 8) * 64 + swt);
        }
#pragma unroll
        for (int nf = 0; nf < 8; nf++) {
            int nr = wn * 64 + nf * 8 + gid;
            bv[nf] = *(const uint4*)(fB + nr * 64 + swt);
        }
        __syncthreads();   // all warps consumed this slot
        if (c + 4 < NCHUNK && tid == 0) {
            uint32_t sdst = sb + OFF_SLOT + slot * STAGE_B;
            MBARRIER_EXPECT_TX(mb, (uint32_t)STAGE_B);
            TMA_LOAD_2D(sdst, &tmA, (c + 4) * BK, r0, mb);
            TMA_LOAD_2D(sdst + A_SZB, &tmB, (c + 4) * BK, n0, mb);
        }

        // instr 0: half-pairs 0,1 (phys k 8t..8t+3)
#pragma unroll
        for (int mf = 0; mf < 4; mf++)
#pragma unroll
            for (int nf = 0; nf < 8; nf++)
                mma_f16(acc[mf][nf], alo[mf].x, ahi[mf].x, alo[mf].y, ahi[mf].y,
                        bv[nf].x, bv[nf].y);
        // instr 1: half-pairs 2,3 (phys k 8t+4..8t+7)
#pragma unroll
        for (int mf = 0; mf < 4; mf++)
#pragma unroll
            for (int nf = 0; nf < 8; nf++)
                mma_f16(acc[mf][nf], alo[mf].z, ahi[mf].z, alo[mf].w, ahi[mf].w,
                        bv[nf].z, bv[nf].w);
    }
    __syncthreads();   // slots dead; red aliases slot 0

    // ---- epilogue: score partial = sum_n v[n] * tanh(acc + hp[n]) ----
    float* red = (float*)(smem + OFF_RED);  // [128][17]
#pragma unroll
    for (int mf = 0; mf < 4; mf++) {
#pragma unroll
        for (int half = 0; half < 2; half++) {
            int r = wm * 64 + mf * 16 + half * 8 + gid;
            float s = 0.f;
#pragma unroll
            for (int nf = 0; nf < 8; nf++) {
                int nl = wn * 64 + nf * 8 + tig * 2;
                float e0 = acc[mf][nf][half * 2 + 0] + shp[nl];
                float e1 = acc[mf][nf][half * 2 + 1] + shp[nl + 1];
                float t0, t1;
                asm("tanh.approx.f32 %0, %1;" : "=f"(t0) : "f"(e0));
                asm("tanh.approx.f32 %0, %1;" : "=f"(t1) : "f"(e1));
                s = fmaf(sv[nl], t0, s);
                s = fmaf(sv[nl + 1], t1, s);
            }
            red[r * 17 + wn * 4 + tig] = s;
        }
    }
    __syncthreads();
    if (tid < BM) {
        float s = 0.f;
#pragma unroll
        for (int t = 0; t < 16; t++) s += red[tid * 17 + t];
        g_pscore[nt * (BB * SS) + r0 + tid] = s;
    }
    __syncthreads();
    if (tid == 0) {
#pragma unroll
        for (int p = 0; p < 4; p++) MBARRIER_INVAL(sb + 16 + p * 8);
    }
}

// ---------------------------------------------------------------------------
// softmax: combine 2 partials, mask, softmax over S. grid(64), 256 threads.
// ---------------------------------------------------------------------------
__global__ void softmax_kernel(const int* __restrict__ mask,
                               float* __restrict__ wout) {
    int b = blockIdx.x;
    __shared__ float sc[SS];
    __shared__ float redbuf[256];
    int tid = threadIdx.x;

    float lmax = -3.402823466e38f;
    for (int s = tid; s < SS; s += 256) {
        int idx = b * SS + s;
        float v = g_pscore[idx] + g_pscore[BB * SS + idx];
        if (mask[idx] == 0) v = -3.402823466e38f;
        sc[s] = v;
        lmax = fmaxf(lmax, v);
    }
    redbuf[tid] = lmax;
    __syncthreads();
    for (int o = 128; o > 0; o >>= 1) {
        if (tid < o) redbuf[tid] = fmaxf(redbuf[tid], redbuf[tid + o]);
        __syncthreads();
    }
    float m = redbuf[0];
    __syncthreads();

    float lsum = 0.f;
    for (int s = tid; s < SS; s += 256) {
        float e = expf(sc[s] - m);
        sc[s] = e;
        lsum += e;
    }
    redbuf[tid] = lsum;
    __syncthreads();
    for (int o = 128; o > 0; o >>= 1) {
        if (tid < o) redbuf[tid] += redbuf[tid + o];
        __syncthreads();
    }
    float inv = 1.f / redbuf[0];
    for (int s = tid; s < SS; s += 256) wout[b * SS + s] = sc[s] * inv;
}

// ---------------------------------------------------------------------------
// context partials from fp16 enc: grid (8, 64), 128 threads; 8 halves/thread.
// ---------------------------------------------------------------------------
__global__ void __launch_bounds__(128) context_part_kernel(
    const float* __restrict__ w) {
    __shared__ float ws[128];
    int sy = blockIdx.x, b = blockIdx.y;
    int e0 = threadIdx.x * 8;
    ws[threadIdx.x] = w[b * SS + sy * 128 + threadIdx.x];
    __syncthreads();
    const __half* base = g_ench + ((size_t)b * SS + sy * 128) * EE + e0;
    float acc[8];
#pragma unroll
    for (int j = 0; j < 8; j++) acc[j] = 0.f;
#pragma unroll 4
    for (int r = 0; r < 128; r++) {
        uint4 v = *(const uint4*)(base + (size_t)r * EE);
        float c = ws[r];
        const uint32_t* p = (const uint32_t*)&v;
#pragma unroll
        for (int q = 0; q < 4; q++) {
            float2 f = __half22float2(*(const __half2*)&p[q]);
            acc[q * 2 + 0] = fmaf(c, f.x, acc[q * 2 + 0]);
            acc[q * 2 + 1] = fmaf(c, f.y, acc[q * 2 + 1]);
        }
    }
    float* dst = &g_ctx_part[((size_t)sy * BB + b) * EE + e0];
    *(float4*)dst = make_float4(acc[0], acc[1], acc[2], acc[3]);
    *(float4*)(dst + 4) = make_float4(acc[4], acc[5], acc[6], acc[7]);
}

__global__ void context_reduce_kernel(float* __restrict__ ctx) {
    int b = blockIdx.y;
    int e = blockIdx.x * 256 + threadIdx.x;
    float s = 0.f;
#pragma unroll
    for (int sy = 0; sy < 8; sy++) s += g_ctx_part[((size_t)sy * BB + b) * EE + e];
    ctx[b * EE + e] = s;
}

// ---------------------------------------------------------------------------
// host: tensormap encode via driver entry point
// ---------------------------------------------------------------------------
typedef CUresult (*EncodeTiledFn)(
    CUtensorMap*, CUtensorMapDataType, cuuint32_t, void*,
    const cuuint64_t*, const cuuint64_t*, const cuuint32_t*, const cuuint32_t*,
    CUtensorMapInterleave, CUtensorMapSwizzle, CUtensorMapL2promotion,
    CUtensorMapFloatOOBfill);

static EncodeTiledFn get_encode_fn() {
    static EncodeTiledFn fn = nullptr;
    if (!fn) {
        void* p = nullptr;
        cudaDriverEntryPointQueryResult st;
#if CUDART_VERSION >= 12050
        cudaGetDriverEntryPointByVersion("cuTensorMapEncodeTiled", &p, 12000,
                                         cudaEnableDefault, &st);
#else
        cudaGetDriverEntryPoint("cuTensorMapEncodeTiled", &p, cudaEnableDefault, &st);
#endif
        fn = (EncodeTiledFn)p;
    }
    return fn;
}

static void make_tmap_f16(CUtensorMap* tm, void* ptr, uint64_t inner,
                          uint64_t outer, uint32_t box_inner, uint32_t box_outer) {
    cuuint64_t dims[2] = {inner, outer};
    cuuint64_t strides[1] = {inner * 2};
    cuuint32_t box[2] = {box_inner, box_outer};
    cuuint32_t es[2] = {1, 1};
    get_encode_fn()(tm, CU_TENSOR_MAP_DATA_TYPE_FLOAT16, 2, ptr, dims, strides,
                    box, es, CU_TENSOR_MAP_INTERLEAVE_NONE,
                    CU_TENSOR_MAP_SWIZZLE_64B, CU_TENSOR_MAP_L2_PROMOTION_L2_128B,
                    CU_TENSOR_MAP_FLOAT_OOB_FILL_NONE);
}

extern "C" void kernel_launch(void* const* d_in, const int* in_sizes, int n_in,
                              void* d_out, int out_size) {
    const float* hidden = (const float*)d_in[0];   // [B, D]
    const float* enc    = (const float*)d_in[1];   // [B, S, E2]
    const int*   mask   = (const int*)d_in[2];     // [B, S]
    const float* attn_W = (const float*)d_in[3];   // [E2+D, D]
    const float* attn_b = (const float*)d_in[4];   // [D]
    const float* v_W    = (const float*)d_in[5];   // [D]

    float* out = (float*)d_out;
    float* ctx = out;            // context [B, E2]
    float* wts = out + BB * EE;  // attn_weights [B, S]

    cudaFuncSetAttribute(scores_mma_kernel,
                         cudaFuncAttributeMaxDynamicSharedMemorySize, SMEM_SIZE);

    void* ench_ptr = nullptr; cudaGetSymbolAddress(&ench_ptr, g_ench);
    void* weth_ptr = nullptr; cudaGetSymbolAddress(&weth_ptr, g_WeTh);

    CUtensorMap tmA, tmB;
    make_tmap_f16(&tmA, ench_ptr, EE, (uint64_t)BB * SS, BK, BM);  // enc fp16 rows
    make_tmap_f16(&tmB, weth_ptr, EE, DD, BK, BN);                 // WeT fp16 rows

    convert_enc<<<(BB * SS * EE) / (256 * 8), 256>>>(enc);
    transpose_we<<<dim3(EE / 32, DD / 32), dim3(32, 8)>>>(attn_W);
    hproj_kernel<<<dim3(DD / 128, BB), 128>>>(hidden, attn_W, attn_b);
    scores_mma_kernel<<<dim3(2, (BB * SS) / BM), 256, SMEM_SIZE>>>(tmA, tmB, v_W);
    softmax_kernel<<<BB, 256>>>(mask, wts);
    context_part_kernel<<<dim3(8, BB), 128>>>(wts);
    context_reduce_kernel<<<dim3(4, BB), 256>>>(ctx);
}

// round 12
// speedup vs baseline: 1.4513x; 1.1055x over previous
#include <cuda_runtime.h>
#include <cuda.h>
#include <cuda_fp16.h>
#include <math.h>
#include <stdint.h>

#define BB 64
#define SS 1024
#define EE 1024
#define DD 512

// ---------------- device scratch ----------------
__device__ float  g_hp[BB * DD];            // h_proj + bias  [B, D]
__device__ __half g_ench[(size_t)BB * SS * EE];  // enc in fp16 (134 MB)
__device__ __half g_WeTh[DD * EE];          // W_e^T in fp16 [D(n), E2(k)]
__device__ float  g_pscore[4 * BB * SS];    // per-n-tile score partials
__device__ float  g_ctx_part[8 * BB * EE];  // context partials

// ---------------- helpers ----------------
__device__ __forceinline__ uint32_t smem_u32(const void* p) {
    uint32_t a;
    asm("{ .reg .u64 t; cvta.to.shared.u64 t, %1; cvt.u32.u64 %0, t; }" : "=r"(a) : "l"(p));
    return a;
}

#define MBARRIER_INIT(addr, cnt) \
    asm volatile("mbarrier.init.shared.b64 [%0], %1;" :: "r"(addr), "r"(cnt) : "memory")
#define MBARRIER_INVAL(addr) \
    asm volatile("mbarrier.inval.shared.b64 [%0];" :: "r"(addr) : "memory")
#define MBARRIER_EXPECT_TX(addr, bytes) \
    asm volatile("mbarrier.arrive.expect_tx.shared.b64 _, [%0], %1;" :: "r"(addr), "r"(bytes) : "memory")
#define MBARRIER_WAIT_PARITY(addr, parity) do {                                     \
    uint32_t _m = (addr), _p = (parity);                                            \
    asm volatile(                                                                   \
        "{\n\t.reg .pred P1;\n\t"                                                   \
        "WL_%=:\n\t"                                                                \
        "mbarrier.try_wait.parity.acquire.cta.shared::cta.b64 P1, [%0], %1, 0x989680;\n\t" \
        "@P1 bra.uni WD_%=;\n\t"                                                    \
        "bra.uni WL_%=;\n\t"                                                        \
        "WD_%=:\n\t}"                                                               \
        :: "r"(_m), "r"(_p) : "memory");                                            \
} while (0)
#define TMA_LOAD_2D(smem, map, cx, cy, mbar)                                        \
    asm volatile(                                                                   \
        "cp.async.bulk.tensor.2d.shared::cta.global.tile.mbarrier::complete_tx::bytes " \
        "[%0], [%1, {%2, %3}], [%4];"                                               \
        :: "r"(smem), "l"(map), "r"(cx), "r"(cy), "r"(mbar) : "memory")

__device__ __forceinline__ uint32_t pack_half2(float lo, float hi) {
    uint32_t r;
    asm("cvt.rn.f16x2.f32 %0, %1, %2;" : "=r"(r) : "f"(hi), "f"(lo));
    return r;
}

__device__ __forceinline__ void mma_f16(float c[4], uint32_t a0, uint32_t a1,
                                        uint32_t a2, uint32_t a3, uint32_t b0,
                                        uint32_t b1) {
    asm volatile(
        "mma.sync.aligned.m16n8k16.row.col.f32.f16.f16.f32 "
        "{%0,%1,%2,%3}, {%4,%5,%6,%7}, {%8,%9}, {%0,%1,%2,%3};"
        : "+f"(c[0]), "+f"(c[1]), "+f"(c[2]), "+f"(c[3])
        : "r"(a0), "r"(a1), "r"(a2), "r"(a3), "r"(b0), "r"(b1));
}

// ---------------- tiling ----------------
#define BM 128
#define BN 128
#define BK 32
#define NCHUNK (EE / BK)        // 32
#define A_SZB (BM * 64)         // 8192 (64B rows, TMA SW64)
#define B_SZB (BN * 64)         // 8192
#define STAGE_B (A_SZB + B_SZB) // 16384
#define OFF_SLOT 1024
#define OFF_SHP (OFF_SLOT + 4 * STAGE_B)      // 66560
#define OFF_SV  (OFF_SHP + BN * 4)
#define OFF_RED OFF_SLOT                      // red[128][17] aliases slot 0 (dead)
#define SMEM_SIZE (OFF_SV + BN * 4)           // 67584 B -> 2 CTAs/SM

// ---------------------------------------------------------------------------
// fused prep: convert enc->fp16 | transpose W_e->fp16 | hproj. 256 thr.
// ---------------------------------------------------------------------------
#define CONV_BLOCKS ((BB * SS * EE) / (256 * 8))   // 16384
#define TRANS_BLOCKS ((EE / 32) * (DD / 32))       // 512
#define HPROJ_BLOCKS ((DD / 256) * BB)             // 128
#define PREP_BLOCKS (CONV_BLOCKS + TRANS_BLOCKS + HPROJ_BLOCKS)

__global__ void __launch_bounds__(256) prep_kernel(
    const float* __restrict__ enc, const float* __restrict__ attn_W,
    const float* __restrict__ attn_b, const float* __restrict__ hidden) {
    __shared__ float sbuf[32 * 33 > 512 ? 32 * 33 : 512];
    int bx = blockIdx.x;
    int tid = threadIdx.x;
    if (bx < CONV_BLOCKS) {
        size_t base = ((size_t)bx * 256 + tid) * 8;
        float4 v0 = *(const float4*)(enc + base);
        float4 v1 = *(const float4*)(enc + base + 4);
        uint4 o;
        o.x = pack_half2(v0.x, v0.y);
        o.y = pack_half2(v0.z, v0.w);
        o.z = pack_half2(v1.x, v1.y);
        o.w = pack_half2(v1.z, v1.w);
        *(uint4*)(&g_ench[base]) = o;
    } else if (bx < CONV_BLOCKS + TRANS_BLOCKS) {
        int id = bx - CONV_BLOCKS;
        int k0 = (id & 31) * 32, d0 = (id >> 5) * 32;
        int x = tid & 31, y = tid >> 5;
        float (*t)[33] = (float(*)[33])sbuf;
        for (int i = y; i < 32; i += 8)
            t[i][x] = attn_W[(size_t)(DD + k0 + i) * DD + d0 + x];
        __syncthreads();
        for (int i = y; i < 32; i += 8)
            g_WeTh[(size_t)(d0 + i) * EE + k0 + x] = __float2half_rn(t[x][i]);
    } else {
        int id = bx - CONV_BLOCKS - TRANS_BLOCKS;
        int b = id >> 1;
        int d = (id & 1) * 256 + tid;
        for (int i = tid; i < DD; i += 256) sbuf[i] = hidden[b * DD + i];
        __syncthreads();
        float acc = attn_b[d];
#pragma unroll 8
        for (int k = 0; k < DD; k++) acc += sbuf[k] * attn_W[k * DD + d];
        g_hp[b * DD + d] = acc;
    }
}

// ---------------------------------------------------------------------------
// scores: fp16 m16n8k16 GEMM (128x128 tile, K=1024), TMA-fed 4-slot pipeline,
// 2 CTAs/SM (launch_bounds(256,2)) -> 4 warps/SMSP.
// Warp grid 2(m) x 4(n), warp tile 64x32. k-slot permutation + SW64 swizzle
// (loop-invariant per-lane offset). grid (4 n-tiles, 512 row-tiles).
// ---------------------------------------------------------------------------
__global__ void __launch_bounds__(256, 2)
scores_mma_kernel(const __grid_constant__ CUtensorMap tmA,
                  const __grid_constant__ CUtensorMap tmB,
                  const float* __restrict__ vW) {
    extern __shared__ char smem[];
    uint32_t sb = smem_u32(smem);
    int tid = threadIdx.x;
    int wid = tid >> 5, lid = tid & 31;
    int gid = lid >> 2, tig = lid & 3;
    int wm = wid >> 2, wn = wid & 3;       // warp grid 2(m) x 4(n)
    int nt = blockIdx.x;                   // n tile (0..3)
    int r0 = blockIdx.y * BM;              // global row
    int b = r0 / SS;
    int n0 = nt * BN;
    int swt = (tig ^ ((gid >> 1) & 3)) * 16;   // loop-invariant swizzled 16B offset

    float* shp = (float*)(smem + OFF_SHP);
    float* sv  = (float*)(smem + OFF_SV);
    for (int i = tid; i < BN; i += 256) {
        shp[i] = g_hp[b * DD + n0 + i];
        sv[i]  = vW[n0 + i];
    }
    if (tid == 0) {
#pragma unroll
        for (int p = 0; p < 4; p++) MBARRIER_INIT(sb + 16 + p * 8, 1);
    }
    __syncthreads();

    if (tid == 0) {
#pragma unroll
        for (int p = 0; p < 4; p++) {
            uint32_t slot = sb + OFF_SLOT + p * STAGE_B;
            MBARRIER_EXPECT_TX(sb + 16 + p * 8, (uint32_t)STAGE_B);
            TMA_LOAD_2D(slot, &tmA, p * BK, r0, sb + 16 + p * 8);
            TMA_LOAD_2D(slot + A_SZB, &tmB, p * BK, n0, sb + 16 + p * 8);
        }
    }

    float acc[4][4][4];
#pragma unroll
    for (int mf = 0; mf < 4; mf++)
#pragma unroll
        for (int nf = 0; nf < 4; nf++)
#pragma unroll
            for (int q = 0; q < 4; q++) acc[mf][nf][q] = 0.f;

#pragma unroll 4
    for (int c = 0; c < NCHUNK; c++) {
        int slot = c & 3;
        uint32_t mb = sb + 16 + slot * 8;
        MBARRIER_WAIT_PARITY(mb, (uint32_t)((c >> 2) & 1));

        const char* fA = smem + OFF_SLOT + slot * STAGE_B;
        const char* fB = fA + A_SZB;

        uint4 alo[4], ahi[4], bv[4];   // 8 halves each: phys k = 8*tig..+7
#pragma unroll
        for (int mf = 0; mf < 4; mf++) {
            int m0 = wm * 64 + mf * 16 + gid;
            alo[mf] = *(const uint4*)(fA + m0 * 64 + swt);
            ahi[mf] = *(const uint4*)(fA + (m0 + 8) * 64 + swt);
        }
#pragma unroll
        for (int nf = 0; nf < 4; nf++) {
            int nr = wn * 32 + nf * 8 + gid;
            bv[nf] = *(const uint4*)(fB + nr * 64 + swt);
        }
        __syncthreads();   // all warps consumed this slot
        if (c + 4 < NCHUNK && tid == 0) {
            uint32_t sdst = sb + OFF_SLOT + slot * STAGE_B;
            MBARRIER_EXPECT_TX(mb, (uint32_t)STAGE_B);
            TMA_LOAD_2D(sdst, &tmA, (c + 4) * BK, r0, mb);
            TMA_LOAD_2D(sdst + A_SZB, &tmB, (c + 4) * BK, n0, mb);
        }

        // instr 0: half-pairs 0,1 (phys k 8t..8t+3)
#pragma unroll
        for (int mf = 0; mf < 4; mf++)
#pragma unroll
            for (int nf = 0; nf < 4; nf++)
                mma_f16(acc[mf][nf], alo[mf].x, ahi[mf].x, alo[mf].y, ahi[mf].y,
                        bv[nf].x, bv[nf].y);
        // instr 1: half-pairs 2,3 (phys k 8t+4..8t+7)
#pragma unroll
        for (int mf = 0; mf < 4; mf++)
#pragma unroll
            for (int nf = 0; nf < 4; nf++)
                mma_f16(acc[mf][nf], alo[mf].z, ahi[mf].z, alo[mf].w, ahi[mf].w,
                        bv[nf].z, bv[nf].w);
    }
    __syncthreads();   // slots dead; red aliases slot 0

    // ---- epilogue: score partial = sum_n v[n] * tanh(acc + hp[n]) ----
    float* red = (float*)(smem + OFF_RED);  // [128][17]
#pragma unroll
    for (int mf = 0; mf < 4; mf++) {
#pragma unroll
        for (int half = 0; half < 2; half++) {
            int r = wm * 64 + mf * 16 + half * 8 + gid;
            float s = 0.f;
#pragma unroll
            for (int nf = 0; nf < 4; nf++) {
                int nl = wn * 32 + nf * 8 + tig * 2;
                float e0 = acc[mf][nf][half * 2 + 0] + shp[nl];
                float e1 = acc[mf][nf][half * 2 + 1] + shp[nl + 1];
                float t0, t1;
                asm("tanh.approx.f32 %0, %1;" : "=f"(t0) : "f"(e0));
                asm("tanh.approx.f32 %0, %1;" : "=f"(t1) : "f"(e1));
                s = fmaf(sv[nl], t0, s);
                s = fmaf(sv[nl + 1], t1, s);
            }
            red[r * 17 + wn * 4 + tig] = s;
        }
    }
    __syncthreads();
    if (tid < BM) {
        float s = 0.f;
#pragma unroll
        for (int t = 0; t < 16; t++) s += red[tid * 17 + t];
        g_pscore[nt * (BB * SS) + r0 + tid] = s;
    }
    __syncthreads();
    if (tid == 0) {
#pragma unroll
        for (int p = 0; p < 4; p++) MBARRIER_INVAL(sb + 16 + p * 8);
    }
}

// ---------------------------------------------------------------------------
// softmax: combine 4 partials, mask, softmax over S. grid(64), 256 threads.
// ---------------------------------------------------------------------------
__global__ void softmax_kernel(const int* __restrict__ mask,
                               float* __restrict__ wout) {
    int b = blockIdx.x;
    __shared__ float sc[SS];
    __shared__ float redbuf[256];
    int tid = threadIdx.x;

    float lmax = -3.402823466e38f;
    for (int s = tid; s < SS; s += 256) {
        int idx = b * SS + s;
        float v = g_pscore[idx] + g_pscore[BB * SS + idx] +
                  g_pscore[2 * BB * SS + idx] + g_pscore[3 * BB * SS + idx];
        if (mask[idx] == 0) v = -3.402823466e38f;
        sc[s] = v;
        lmax = fmaxf(lmax, v);
    }
    redbuf[tid] = lmax;
    __syncthreads();
    for (int o = 128; o > 0; o >>= 1) {
        if (tid < o) redbuf[tid] = fmaxf(redbuf[tid], redbuf[tid + o]);
        __syncthreads();
    }
    float m = redbuf[0];
    __syncthreads();

    float lsum = 0.f;
    for (int s = tid; s < SS; s += 256) {
        float e = expf(sc[s] - m);
        sc[s] = e;
        lsum += e;
    }
    redbuf[tid] = lsum;
    __syncthreads();
    for (int o = 128; o > 0; o >>= 1) {
        if (tid < o) redbuf[tid] += redbuf[tid + o];
        __syncthreads();
    }
    float inv = 1.f / redbuf[0];
    for (int s = tid; s < SS; s += 256) wout[b * SS + s] = sc[s] * inv;
}

// ---------------------------------------------------------------------------
// context partials from fp16 enc: grid (8, 64), 128 threads; 8 halves/thread.
// ---------------------------------------------------------------------------
__global__ void __launch_bounds__(128) context_part_kernel(
    const float* __restrict__ w) {
    __shared__ float ws[128];
    int sy = blockIdx.x, b = blockIdx.y;
    int e0 = threadIdx.x * 8;
    ws[threadIdx.x] = w[b * SS + sy * 128 + threadIdx.x];
    __syncthreads();
    const __half* base = g_ench + ((size_t)b * SS + sy * 128) * EE + e0;
    float acc[8];
#pragma unroll
    for (int j = 0; j < 8; j++) acc[j] = 0.f;
#pragma unroll 4
    for (int r = 0; r < 128; r++) {
        uint4 v = *(const uint4*)(base + (size_t)r * EE);
        float c = ws[r];
        const uint32_t* p = (const uint32_t*)&v;
#pragma unroll
        for (int q = 0; q < 4; q++) {
            float2 f = __half22float2(*(const __half2*)&p[q]);
            acc[q * 2 + 0] = fmaf(c, f.x, acc[q * 2 + 0]);
            acc[q * 2 + 1] = fmaf(c, f.y, acc[q * 2 + 1]);
        }
    }
    float* dst = &g_ctx_part[((size_t)sy * BB + b) * EE + e0];
    *(float4*)dst = make_float4(acc[0], acc[1], acc[2], acc[3]);
    *(float4*)(dst + 4) = make_float4(acc[4], acc[5], acc[6], acc[7]);
}

__global__ void context_reduce_kernel(float* __restrict__ ctx) {
    int b = blockIdx.y;
    int e = blockIdx.x * 256 + threadIdx.x;
    float s = 0.f;
#pragma unroll
    for (int sy = 0; sy < 8; sy++) s += g_ctx_part[((size_t)sy * BB + b) * EE + e];
    ctx[b * EE + e] = s;
}

// ---------------------------------------------------------------------------
// host: tensormap encode via driver entry point
// ---------------------------------------------------------------------------
typedef CUresult (*EncodeTiledFn)(
    CUtensorMap*, CUtensorMapDataType, cuuint32_t, void*,
    const cuuint64_t*, const cuuint64_t*, const cuuint32_t*, const cuuint32_t*,
    CUtensorMapInterleave, CUtensorMapSwizzle, CUtensorMapL2promotion,
    CUtensorMapFloatOOBfill);

static EncodeTiledFn get_encode_fn() {
    static EncodeTiledFn fn = nullptr;
    if (!fn) {
        void* p = nullptr;
        cudaDriverEntryPointQueryResult st;
#if CUDART_VERSION >= 12050
        cudaGetDriverEntryPointByVersion("cuTensorMapEncodeTiled", &p, 12000,
                                         cudaEnableDefault, &st);
#else
        cudaGetDriverEntryPoint("cuTensorMapEncodeTiled", &p, cudaEnableDefault, &st);
#endif
        fn = (EncodeTiledFn)p;
    }
    return fn;
}

static void make_tmap_f16(CUtensorMap* tm, void* ptr, uint64_t inner,
                          uint64_t outer, uint32_t box_inner, uint32_t box_outer) {
    cuuint64_t dims[2] = {inner, outer};
    cuuint64_t strides[1] = {inner * 2};
    cuuint32_t box[2] = {box_inner, box_outer};
    cuuint32_t es[2] = {1, 1};
    get_encode_fn()(tm, CU_TENSOR_MAP_DATA_TYPE_FLOAT16, 2, ptr, dims, strides,
                    box, es, CU_TENSOR_MAP_INTERLEAVE_NONE,
                    CU_TENSOR_MAP_SWIZZLE_64B, CU_TENSOR_MAP_L2_PROMOTION_L2_128B,
                    CU_TENSOR_MAP_FLOAT_OOB_FILL_NONE);
}

extern "C" void kernel_launch(void* const* d_in, const int* in_sizes, int n_in,
                              void* d_out, int out_size) {
    const float* hidden = (const float*)d_in[0];   // [B, D]
    const float* enc    = (const float*)d_in[1];   // [B, S, E2]
    const int*   mask   = (const int*)d_in[2];     // [B, S]
    const float* attn_W = (const float*)d_in[3];   // [E2+D, D]
    const float* attn_b = (const float*)d_in[4];   // [D]
    const float* v_W    = (const float*)d_in[5];   // [D]

    float* out = (float*)d_out;
    float* ctx = out;            // context [B, E2]
    float* wts = out + BB * EE;  // attn_weights [B, S]

    cudaFuncSetAttribute(scores_mma_kernel,
                         cudaFuncAttributeMaxDynamicSharedMemorySize, SMEM_SIZE);

    void* ench_ptr = nullptr; cudaGetSymbolAddress(&ench_ptr, g_ench);
    void* weth_ptr = nullptr; cudaGetSymbolAddress(&weth_ptr, g_WeTh);

    CUtensorMap tmA, tmB;
    make_tmap_f16(&tmA, ench_ptr, EE, (uint64_t)BB * SS, BK, BM);  // enc fp16 rows
    make_tmap_f16(&tmB, weth_ptr, EE, DD, BK, BN);                 // WeT fp16 rows

    prep_kernel<<<PREP_BLOCKS, 256>>>(enc, attn_W, attn_b, hidden);
    scores_mma_kernel<<<dim3(4, (BB * SS) / BM), 256, SMEM_SIZE>>>(tmA, tmB, v_W);
    softmax_kernel<<<BB, 256>>>(mask, wts);
    context_part_kernel<<<dim3(8, BB), 128>>>(wts);
    context_reduce_kernel<<<dim3(4, BB), 256>>>(ctx);
}

// round 13
// speedup vs baseline: 1.5110x; 1.0411x over previous
#include <cuda_runtime.h>
#include <cuda.h>
#include <cuda_fp16.h>
#include <math.h>
#include <stdint.h>

#define BB 64
#define SS 1024
#define EE 1024
#define DD 512

// ---------------- device scratch ----------------
__device__ float  g_hp[BB * DD];            // h_proj + bias  [B, D]
__device__ __half g_ench[(size_t)BB * SS * EE];  // enc in fp16 (134 MB)
__device__ __half g_WeTh[DD * EE];          // W_e^T in fp16 [D(n), E2(k)]
__device__ float  g_pscore[4 * BB * SS];    // per-n-tile score partials
__device__ float  g_ctx_part[16 * BB * EE]; // context partials (16 S-slices)

// ---------------- helpers ----------------
__device__ __forceinline__ uint32_t smem_u32(const void* p) {
    uint32_t a;
    asm("{ .reg .u64 t; cvta.to.shared.u64 t, %1; cvt.u32.u64 %0, t; }" : "=r"(a) : "l"(p));
    return a;
}

#define MBARRIER_INIT(addr, cnt) \
    asm volatile("mbarrier.init.shared.b64 [%0], %1;" :: "r"(addr), "r"(cnt) : "memory")
#define MBARRIER_INVAL(addr) \
    asm volatile("mbarrier.inval.shared.b64 [%0];" :: "r"(addr) : "memory")
#define MBARRIER_EXPECT_TX(addr, bytes) \
    asm volatile("mbarrier.arrive.expect_tx.shared.b64 _, [%0], %1;" :: "r"(addr), "r"(bytes) : "memory")
#define MBARRIER_WAIT_PARITY(addr, parity) do {                                     \
    uint32_t _m = (addr), _p = (parity);                                            \
    asm volatile(                                                                   \
        "{\n\t.reg .pred P1;\n\t"                                                   \
        "WL_%=:\n\t"                                                                \
        "mbarrier.try_wait.parity.acquire.cta.shared::cta.b64 P1, [%0], %1, 0x989680;\n\t" \
        "@P1 bra.uni WD_%=;\n\t"                                                    \
        "bra.uni WL_%=;\n\t"                                                        \
        "WD_%=:\n\t}"                                                               \
        :: "r"(_m), "r"(_p) : "memory");                                            \
} while (0)
#define TMA_LOAD_2D(smem, map, cx, cy, mbar)                                        \
    asm volatile(                                                                   \
        "cp.async.bulk.tensor.2d.shared::cta.global.tile.mbarrier::complete_tx::bytes " \
        "[%0], [%1, {%2, %3}], [%4];"                                               \
        :: "r"(smem), "l"(map), "r"(cx), "r"(cy), "r"(mbar) : "memory")

__device__ __forceinline__ uint32_t pack_half2(float lo, float hi) {
    uint32_t r;
    asm("cvt.rn.f16x2.f32 %0, %1, %2;" : "=r"(r) : "f"(hi), "f"(lo));
    return r;
}

__device__ __forceinline__ void mma_f16(float c[4], uint32_t a0, uint32_t a1,
                                        uint32_t a2, uint32_t a3, uint32_t b0,
                                        uint32_t b1) {
    asm volatile(
        "mma.sync.aligned.m16n8k16.row.col.f32.f16.f16.f32 "
        "{%0,%1,%2,%3}, {%4,%5,%6,%7}, {%8,%9}, {%0,%1,%2,%3};"
        : "+f"(c[0]), "+f"(c[1]), "+f"(c[2]), "+f"(c[3])
        : "r"(a0), "r"(a1), "r"(a2), "r"(a3), "r"(b0), "r"(b1));
}

// ---------------- tiling ----------------
#define BM 128
#define BN 128
#define BK 32
#define NCHUNK (EE / BK)        // 32
#define A_SZB (BM * 64)         // 8192 (64B rows, TMA SW64)
#define B_SZB (BN * 64)         // 8192
#define STAGE_B (A_SZB + B_SZB) // 16384
#define OFF_SLOT 1024
#define OFF_SHP (OFF_SLOT + 4 * STAGE_B)      // 66560
#define OFF_SV  (OFF_SHP + BN * 4)
#define OFF_RED OFF_SLOT                      // red[128][17] aliases slot 0 (dead)
#define SMEM_SIZE (OFF_SV + BN * 4)           // 67584 B -> 2 CTAs/SM

// ---------------------------------------------------------------------------
// fused prep: convert enc->fp16 | transpose W_e->fp16 | hproj. 256 thr.
// ---------------------------------------------------------------------------
#define CONV_BLOCKS ((BB * SS * EE) / (256 * 8))   // 16384
#define TRANS_BLOCKS ((EE / 32) * (DD / 32))       // 512
#define HPROJ_BLOCKS ((DD / 256) * BB)             // 128
#define PREP_BLOCKS (CONV_BLOCKS + TRANS_BLOCKS + HPROJ_BLOCKS)

__global__ void __launch_bounds__(256) prep_kernel(
    const float* __restrict__ enc, const float* __restrict__ attn_W,
    const float* __restrict__ attn_b, const float* __restrict__ hidden) {
    __shared__ float sbuf[32 * 33 > 512 ? 32 * 33 : 512];
    int bx = blockIdx.x;
    int tid = threadIdx.x;
    if (bx < CONV_BLOCKS) {
        size_t base = ((size_t)bx * 256 + tid) * 8;
        float4 v0 = __ldcs((const float4*)(enc + base));      // f32 enc never re-read
        float4 v1 = __ldcs((const float4*)(enc + base + 4));
        uint4 o;
        o.x = pack_half2(v0.x, v0.y);
        o.y = pack_half2(v0.z, v0.w);
        o.z = pack_half2(v1.x, v1.y);
        o.w = pack_half2(v1.z, v1.w);
        *(uint4*)(&g_ench[base]) = o;
    } else if (bx < CONV_BLOCKS + TRANS_BLOCKS) {
        int id = bx - CONV_BLOCKS;
        int k0 = (id & 31) * 32, d0 = (id >> 5) * 32;
        int x = tid & 31, y = tid >> 5;
        float (*t)[33] = (float(*)[33])sbuf;
        for (int i = y; i < 32; i += 8)
            t[i][x] = attn_W[(size_t)(DD + k0 + i) * DD + d0 + x];
        __syncthreads();
        for (int i = y; i < 32; i += 8)
            g_WeTh[(size_t)(d0 + i) * EE + k0 + x] = __float2half_rn(t[x][i]);
    } else {
        int id = bx - CONV_BLOCKS - TRANS_BLOCKS;
        int b = id >> 1;
        int d = (id & 1) * 256 + tid;
        for (int i = tid; i < DD; i += 256) sbuf[i] = hidden[b * DD + i];
        __syncthreads();
        float acc = attn_b[d];
#pragma unroll 8
        for (int k = 0; k < DD; k++) acc += sbuf[k] * attn_W[k * DD + d];
        g_hp[b * DD + d] = acc;
    }
}

// ---------------------------------------------------------------------------
// scores: fp16 m16n8k16 GEMM (128x128 tile, K=1024), TMA-fed 4-slot pipeline,
// 2 CTAs/SM (launch_bounds(256,2)) -> 4 warps/SMSP.  [unchanged from R12]
// ---------------------------------------------------------------------------
__global__ void __launch_bounds__(256, 2)
scores_mma_kernel(const __grid_constant__ CUtensorMap tmA,
                  const __grid_constant__ CUtensorMap tmB,
                  const float* __restrict__ vW) {
    extern __shared__ char smem[];
    uint32_t sb = smem_u32(smem);
    int tid = threadIdx.x;
    int wid = tid >> 5, lid = tid & 31;
    int gid = lid >> 2, tig = lid & 3;
    int wm = wid >> 2, wn = wid & 3;       // warp grid 2(m) x 4(n)
    int nt = blockIdx.x;                   // n tile (0..3)
    int r0 = blockIdx.y * BM;              // global row
    int b = r0 / SS;
    int n0 = nt * BN;
    int swt = (tig ^ ((gid >> 1) & 3)) * 16;   // loop-invariant swizzled 16B offset

    float* shp = (float*)(smem + OFF_SHP);
    float* sv  = (float*)(smem + OFF_SV);
    for (int i = tid; i < BN; i += 256) {
        shp[i] = g_hp[b * DD + n0 + i];
        sv[i]  = vW[n0 + i];
    }
    if (tid == 0) {
#pragma unroll
        for (int p = 0; p < 4; p++) MBARRIER_INIT(sb + 16 + p * 8, 1);
    }
    __syncthreads();

    if (tid == 0) {
#pragma unroll
        for (int p = 0; p < 4; p++) {
            uint32_t slot = sb + OFF_SLOT + p * STAGE_B;
            MBARRIER_EXPECT_TX(sb + 16 + p * 8, (uint32_t)STAGE_B);
            TMA_LOAD_2D(slot, &tmA, p * BK, r0, sb + 16 + p * 8);
            TMA_LOAD_2D(slot + A_SZB, &tmB, p * BK, n0, sb + 16 + p * 8);
        }
    }

    float acc[4][4][4];
#pragma unroll
    for (int mf = 0; mf < 4; mf++)
#pragma unroll
        for (int nf = 0; nf < 4; nf++)
#pragma unroll
            for (int q = 0; q < 4; q++) acc[mf][nf][q] = 0.f;

#pragma unroll 4
    for (int c = 0; c < NCHUNK; c++) {
        int slot = c & 3;
        uint32_t mb = sb + 16 + slot * 8;
        MBARRIER_WAIT_PARITY(mb, (uint32_t)((c >> 2) & 1));

        const char* fA = smem + OFF_SLOT + slot * STAGE_B;
        const char* fB = fA + A_SZB;

        uint4 alo[4], ahi[4], bv[4];   // 8 halves each: phys k = 8*tig..+7
#pragma unroll
        for (int mf = 0; mf < 4; mf++) {
            int m0 = wm * 64 + mf * 16 + gid;
            alo[mf] = *(const uint4*)(fA + m0 * 64 + swt);
            ahi[mf] = *(const uint4*)(fA + (m0 + 8) * 64 + swt);
        }
#pragma unroll
        for (int nf = 0; nf < 4; nf++) {
            int nr = wn * 32 + nf * 8 + gid;
            bv[nf] = *(const uint4*)(fB + nr * 64 + swt);
        }
        __syncthreads();   // all warps consumed this slot
        if (c + 4 < NCHUNK && tid == 0) {
            uint32_t sdst = sb + OFF_SLOT + slot * STAGE_B;
            MBARRIER_EXPECT_TX(mb, (uint32_t)STAGE_B);
            TMA_LOAD_2D(sdst, &tmA, (c + 4) * BK, r0, mb);
            TMA_LOAD_2D(sdst + A_SZB, &tmB, (c + 4) * BK, n0, mb);
        }

        // instr 0: half-pairs 0,1 (phys k 8t..8t+3)
#pragma unroll
        for (int mf = 0; mf < 4; mf++)
#pragma unroll
            for (int nf = 0; nf < 4; nf++)
                mma_f16(acc[mf][nf], alo[mf].x, ahi[mf].x, alo[mf].y, ahi[mf].y,
                        bv[nf].x, bv[nf].y);
        // instr 1: half-pairs 2,3 (phys k 8t+4..8t+7)
#pragma unroll
        for (int mf = 0; mf < 4; mf++)
#pragma unroll
            for (int nf = 0; nf < 4; nf++)
                mma_f16(acc[mf][nf], alo[mf].z, ahi[mf].z, alo[mf].w, ahi[mf].w,
                        bv[nf].z, bv[nf].w);
    }
    __syncthreads();   // slots dead; red aliases slot 0

    // ---- epilogue: score partial = sum_n v[n] * tanh(acc + hp[n]) ----
    float* red = (float*)(smem + OFF_RED);  // [128][17]
#pragma unroll
    for (int mf = 0; mf < 4; mf++) {
#pragma unroll
        for (int half = 0; half < 2; half++) {
            int r = wm * 64 + mf * 16 + half * 8 + gid;
            float s = 0.f;
#pragma unroll
            for (int nf = 0; nf < 4; nf++) {
                int nl = wn * 32 + nf * 8 + tig * 2;
                float e0 = acc[mf][nf][half * 2 + 0] + shp[nl];
                float e1 = acc[mf][nf][half * 2 + 1] + shp[nl + 1];
                float t0, t1;
                asm("tanh.approx.f32 %0, %1;" : "=f"(t0) : "f"(e0));
                asm("tanh.approx.f32 %0, %1;" : "=f"(t1) : "f"(e1));
                s = fmaf(sv[nl], t0, s);
                s = fmaf(sv[nl + 1], t1, s);
            }
            red[r * 17 + wn * 4 + tig] = s;
        }
    }
    __syncthreads();
    if (tid < BM) {
        float s = 0.f;
#pragma unroll
        for (int t = 0; t < 16; t++) s += red[tid * 17 + t];
        g_pscore[nt * (BB * SS) + r0 + tid] = s;
    }
    __syncthreads();
    if (tid == 0) {
#pragma unroll
        for (int p = 0; p < 4; p++) MBARRIER_INVAL(sb + 16 + p * 8);
    }
}

// ---------------------------------------------------------------------------
// softmax: combine 4 partials, mask, softmax over S. grid(64), 256 threads.
// ---------------------------------------------------------------------------
__global__ void softmax_kernel(const int* __restrict__ mask,
                               float* __restrict__ wout) {
    int b = blockIdx.x;
    __shared__ float sc[SS];
    __shared__ float redbuf[256];
    int tid = threadIdx.x;

    float lmax = -3.402823466e38f;
    for (int s = tid; s < SS; s += 256) {
        int idx = b * SS + s;
        float v = g_pscore[idx] + g_pscore[BB * SS + idx] +
                  g_pscore[2 * BB * SS + idx] + g_pscore[3 * BB * SS + idx];
        if (mask[idx] == 0) v = -3.402823466e38f;
        sc[s] = v;
        lmax = fmaxf(lmax, v);
    }
    redbuf[tid] = lmax;
    __syncthreads();
    for (int o = 128; o > 0; o >>= 1) {
        if (tid < o) redbuf[tid] = fmaxf(redbuf[tid], redbuf[tid + o]);
        __syncthreads();
    }
    float m = redbuf[0];
    __syncthreads();

    float lsum = 0.f;
    for (int s = tid; s < SS; s += 256) {
        float e = expf(sc[s] - m);
        sc[s] = e;
        lsum += e;
    }
    redbuf[tid] = lsum;
    __syncthreads();
    for (int o = 128; o > 0; o >>= 1) {
        if (tid < o) redbuf[tid] += redbuf[tid + o];
        __syncthreads();
    }
    float inv = 1.f / redbuf[0];
    for (int s = tid; s < SS; s += 256) wout[b * SS + s] = sc[s] * inv;
}

// ---------------------------------------------------------------------------
// context partials from fp16 enc: grid (16, 64), 64 rows/slice, 128 threads,
// 8 halves/thread. 1024 blocks -> ~8 resident blocks/SM for DRAM latency.
// ---------------------------------------------------------------------------
__global__ void __launch_bounds__(128) context_part_kernel(
    const float* __restrict__ w) {
    __shared__ float ws[64];
    int sy = blockIdx.x, b = blockIdx.y;
    int e0 = threadIdx.x * 8;
    if (threadIdx.x < 64) ws[threadIdx.x] = w[b * SS + sy * 64 + threadIdx.x];
    __syncthreads();
    const __half* base = g_ench + ((size_t)b * SS + sy * 64) * EE + e0;
    float acc[8];
#pragma unroll
    for (int j = 0; j < 8; j++) acc[j] = 0.f;
#pragma unroll 4
    for (int r = 0; r < 64; r++) {
        uint4 v = *(const uint4*)(base + (size_t)r * EE);
        float c = ws[r];
        const uint32_t* p = (const uint32_t*)&v;
#pragma unroll
        for (int q = 0; q < 4; q++) {
            float2 f = __half22float2(*(const __half2*)&p[q]);
            acc[q * 2 + 0] = fmaf(c, f.x, acc[q * 2 + 0]);
            acc[q * 2 + 1] = fmaf(c, f.y, acc[q * 2 + 1]);
        }
    }
    float* dst = &g_ctx_part[((size_t)sy * BB + b) * EE + e0];
    *(float4*)dst = make_float4(acc[0], acc[1], acc[2], acc[3]);
    *(float4*)(dst + 4) = make_float4(acc[4], acc[5], acc[6], acc[7]);
}

__global__ void context_reduce_kernel(float* __restrict__ ctx) {
    int b = blockIdx.y;
    int e = blockIdx.x * 256 + threadIdx.x;
    float s = 0.f;
#pragma unroll
    for (int sy = 0; sy < 16; sy++) s += g_ctx_part[((size_t)sy * BB + b) * EE + e];
    ctx[b * EE + e] = s;
}

// ---------------------------------------------------------------------------
// host: tensormap encode via driver entry point
// ---------------------------------------------------------------------------
typedef CUresult (*EncodeTiledFn)(
    CUtensorMap*, CUtensorMapDataType, cuuint32_t, void*,
    const cuuint64_t*, const cuuint64_t*, const cuuint32_t*, const cuuint32_t*,
    CUtensorMapInterleave, CUtensorMapSwizzle, CUtensorMapL2promotion,
    CUtensorMapFloatOOBfill);

static EncodeTiledFn get_encode_fn() {
    static EncodeTiledFn fn = nullptr;
    if (!fn) {
        void* p = nullptr;
        cudaDriverEntryPointQueryResult st;
#if CUDART_VERSION >= 12050
        cudaGetDriverEntryPointByVersion("cuTensorMapEncodeTiled", &p, 12000,
                                         cudaEnableDefault, &st);
#else
        cudaGetDriverEntryPoint("cuTensorMapEncodeTiled", &p, cudaEnableDefault, &st);
#endif
        fn = (EncodeTiledFn)p;
    }
    return fn;
}

static void make_tmap_f16(CUtensorMap* tm, void* ptr, uint64_t inner,
                          uint64_t outer, uint32_t box_inner, uint32_t box_outer) {
    cuuint64_t dims[2] = {inner, outer};
    cuuint64_t strides[1] = {inner * 2};
    cuuint32_t box[2] = {box_inner, box_outer};
    cuuint32_t es[2] = {1, 1};
    get_encode_fn()(tm, CU_TENSOR_MAP_DATA_TYPE_FLOAT16, 2, ptr, dims, strides,
                    box, es, CU_TENSOR_MAP_INTERLEAVE_NONE,
                    CU_TENSOR_MAP_SWIZZLE_64B, CU_TENSOR_MAP_L2_PROMOTION_L2_128B,
                    CU_TENSOR_MAP_FLOAT_OOB_FILL_NONE);
}

extern "C" void kernel_launch(void* const* d_in, const int* in_sizes, int n_in,
                              void* d_out, int out_size) {
    const float* hidden = (const float*)d_in[0];   // [B, D]
    const float* enc    = (const float*)d_in[1];   // [B, S, E2]
    const int*   mask   = (const int*)d_in[2];     // [B, S]
    const float* attn_W = (const float*)d_in[3];   // [E2+D, D]
    const float* attn_b = (const float*)d_in[4];   // [D]
    const float* v_W    = (const float*)d_in[5];   // [D]

    float* out = (float*)d_out;
    float* ctx = out;            // context [B, E2]
    float* wts = out + BB * EE;  // attn_weights [B, S]

    cudaFuncSetAttribute(scores_mma_kernel,
                         cudaFuncAttributeMaxDynamicSharedMemorySize, SMEM_SIZE);

    void* ench_ptr = nullptr; cudaGetSymbolAddress(&ench_ptr, g_ench);
    void* weth_ptr = nullptr; cudaGetSymbolAddress(&weth_ptr, g_WeTh);

    CUtensorMap tmA, tmB;
    make_tmap_f16(&tmA, ench_ptr, EE, (uint64_t)BB * SS, BK, BM);  // enc fp16 rows
    make_tmap_f16(&tmB, weth_ptr, EE, DD, BK, BN);                 // WeT fp16 rows

    prep_kernel<<<PREP_BLOCKS, 256>>>(enc, attn_W, attn_b, hidden);
    scores_mma_kernel<<<dim3(4, (BB * SS) / BM), 256, SMEM_SIZE>>>(tmA, tmB, v_W);
    softmax_kernel<<<BB, 256>>>(mask, wts);
    context_part_kernel<<<dim3(16, BB), 128>>>(wts);
    context_reduce_kernel<<<dim3(4, BB), 256>>>(ctx);
}

// round 14
// speedup vs baseline: 1.5289x; 1.0118x over previous
#include <cuda_runtime.h>
#include <cuda.h>
#include <cuda_fp16.h>
#include <math.h>
#include <stdint.h>

#define BB 64
#define SS 1024
#define EE 1024
#define DD 512

// ---------------- device scratch ----------------
__device__ float  g_hp[BB * DD];            // h_proj + bias  [B, D]
__device__ __half g_ench[(size_t)BB * SS * EE];  // enc in fp16 (134 MB)
__device__ __half g_WeTh[DD * EE];          // W_e^T in fp16 [D(n), E2(k)]
__device__ float  g_pscore[4 * BB * SS];    // per-n-tile score partials
__device__ float  g_ctx_part[16 * BB * EE]; // context partials (16 S-slices)

// ---------------- helpers ----------------
__device__ __forceinline__ uint32_t smem_u32(const void* p) {
    uint32_t a;
    asm("{ .reg .u64 t; cvta.to.shared.u64 t, %1; cvt.u32.u64 %0, t; }" : "=r"(a) : "l"(p));
    return a;
}

#define MBARRIER_INIT(addr, cnt) \
    asm volatile("mbarrier.init.shared.b64 [%0], %1;" :: "r"(addr), "r"(cnt) : "memory")
#define MBARRIER_INVAL(addr) \
    asm volatile("mbarrier.inval.shared.b64 [%0];" :: "r"(addr) : "memory")
#define MBARRIER_EXPECT_TX(addr, bytes) \
    asm volatile("mbarrier.arrive.expect_tx.shared.b64 _, [%0], %1;" :: "r"(addr), "r"(bytes) : "memory")
#define MBARRIER_WAIT_PARITY(addr, parity) do {                                     \
    uint32_t _m = (addr), _p = (parity);                                            \
    asm volatile(                                                                   \
        "{\n\t.reg .pred P1;\n\t"                                                   \
        "WL_%=:\n\t"                                                                \
        "mbarrier.try_wait.parity.acquire.cta.shared::cta.b64 P1, [%0], %1, 0x989680;\n\t" \
        "@P1 bra.uni WD_%=;\n\t"                                                    \
        "bra.uni WL_%=;\n\t"                                                        \
        "WD_%=:\n\t}"                                                               \
        :: "r"(_m), "r"(_p) : "memory");                                            \
} while (0)
#define TMA_LOAD_2D(smem, map, cx, cy, mbar)                                        \
    asm volatile(                                                                   \
        "cp.async.bulk.tensor.2d.shared::cta.global.tile.mbarrier::complete_tx::bytes " \
        "[%0], [%1, {%2, %3}], [%4];"                                               \
        :: "r"(smem), "l"(map), "r"(cx), "r"(cy), "r"(mbar) : "memory")

__device__ __forceinline__ uint32_t pack_half2(float lo, float hi) {
    uint32_t r;
    asm("cvt.rn.f16x2.f32 %0, %1, %2;" : "=r"(r) : "f"(hi), "f"(lo));
    return r;
}

__device__ __forceinline__ void mma_f16(float c[4], uint32_t a0, uint32_t a1,
                                        uint32_t a2, uint32_t a3, uint32_t b0,
                                        uint32_t b1) {
    asm volatile(
        "mma.sync.aligned.m16n8k16.row.col.f32.f16.f16.f32 "
        "{%0,%1,%2,%3}, {%4,%5,%6,%7}, {%8,%9}, {%0,%1,%2,%3};"
        : "+f"(c[0]), "+f"(c[1]), "+f"(c[2]), "+f"(c[3])
        : "r"(a0), "r"(a1), "r"(a2), "r"(a3), "r"(b0), "r"(b1));
}

// ---------------- tiling ----------------
#define BM 128
#define BN 128
#define BK 32
#define NCHUNK (EE / BK)        // 32
#define A_SZB (BM * 64)         // 8192 (64B rows, TMA SW64)
#define B_SZB (BN * 64)         // 8192
#define STAGE_B (A_SZB + B_SZB) // 16384
#define OFF_SLOT 1024
#define OFF_SHP (OFF_SLOT + 4 * STAGE_B)      // 66560
#define OFF_SV  (OFF_SHP + BN * 4)
#define OFF_RED OFF_SLOT                      // red[128][17] aliases slot 0 (dead)
#define SMEM_SIZE (OFF_SV + BN * 4)           // 67584 B -> 2 CTAs/SM

// ---------------------------------------------------------------------------
// fused prep: convert enc->fp16 | transpose W_e->fp16 | hproj. 256 thr.
// ---------------------------------------------------------------------------
#define CONV_BLOCKS ((BB * SS * EE) / (256 * 8))   // 16384
#define TRANS_BLOCKS ((EE / 32) * (DD / 32))       // 512
#define HPROJ_BLOCKS ((DD / 256) * BB)             // 128
#define PREP_BLOCKS (CONV_BLOCKS + TRANS_BLOCKS + HPROJ_BLOCKS)

__global__ void __launch_bounds__(256) prep_kernel(
    const float* __restrict__ enc, const float* __restrict__ attn_W,
    const float* __restrict__ attn_b, const float* __restrict__ hidden) {
    __shared__ float sbuf[32 * 33 > 512 ? 32 * 33 : 512];
    int bx = blockIdx.x;
    int tid = threadIdx.x;
    if (bx < CONV_BLOCKS) {
        size_t base = ((size_t)bx * 256 + tid) * 8;
        float4 v0 = __ldcs((const float4*)(enc + base));      // f32 enc never re-read
        float4 v1 = __ldcs((const float4*)(enc + base + 4));
        uint4 o;
        o.x = pack_half2(v0.x, v0.y);
        o.y = pack_half2(v0.z, v0.w);
        o.z = pack_half2(v1.x, v1.y);
        o.w = pack_half2(v1.z, v1.w);
        __stcs((uint4*)(&g_ench[base]), o);                   // streaming store
    } else if (bx < CONV_BLOCKS + TRANS_BLOCKS) {
        int id = bx - CONV_BLOCKS;
        int k0 = (id & 31) * 32, d0 = (id >> 5) * 32;
        int x = tid & 31, y = tid >> 5;
        float (*t)[33] = (float(*)[33])sbuf;
        for (int i = y; i < 32; i += 8)
            t[i][x] = attn_W[(size_t)(DD + k0 + i) * DD + d0 + x];
        __syncthreads();
        for (int i = y; i < 32; i += 8)
            g_WeTh[(size_t)(d0 + i) * EE + k0 + x] = __float2half_rn(t[x][i]);
    } else {
        int id = bx - CONV_BLOCKS - TRANS_BLOCKS;
        int b = id >> 1;
        int d = (id & 1) * 256 + tid;
        for (int i = tid; i < DD; i += 256) sbuf[i] = hidden[b * DD + i];
        __syncthreads();
        float acc = attn_b[d];
#pragma unroll 8
        for (int k = 0; k < DD; k++) acc += sbuf[k] * attn_W[k * DD + d];
        g_hp[b * DD + d] = acc;
    }
}

// ---------------------------------------------------------------------------
// scores: fp16 m16n8k16 GEMM (128x128 tile, K=1024), TMA-fed 4-slot pipeline,
// 2 CTAs/SM (launch_bounds(256,2)) -> 4 warps/SMSP.  [unchanged — proven]
// ---------------------------------------------------------------------------
__global__ void __launch_bounds__(256, 2)
scores_mma_kernel(const __grid_constant__ CUtensorMap tmA,
                  const __grid_constant__ CUtensorMap tmB,
                  const float* __restrict__ vW) {
    extern __shared__ char smem[];
    uint32_t sb = smem_u32(smem);
    int tid = threadIdx.x;
    int wid = tid >> 5, lid = tid & 31;
    int gid = lid >> 2, tig = lid & 3;
    int wm = wid >> 2, wn = wid & 3;       // warp grid 2(m) x 4(n)
    int nt = blockIdx.x;                   // n tile (0..3)
    int r0 = blockIdx.y * BM;              // global row
    int b = r0 / SS;
    int n0 = nt * BN;
    int swt = (tig ^ ((gid >> 1) & 3)) * 16;   // loop-invariant swizzled 16B offset

    float* shp = (float*)(smem + OFF_SHP);
    float* sv  = (float*)(smem + OFF_SV);
    for (int i = tid; i < BN; i += 256) {
        shp[i] = g_hp[b * DD + n0 + i];
        sv[i]  = vW[n0 + i];
    }
    if (tid == 0) {
#pragma unroll
        for (int p = 0; p < 4; p++) MBARRIER_INIT(sb + 16 + p * 8, 1);
    }
    __syncthreads();

    if (tid == 0) {
#pragma unroll
        for (int p = 0; p < 4; p++) {
            uint32_t slot = sb + OFF_SLOT + p * STAGE_B;
            MBARRIER_EXPECT_TX(sb + 16 + p * 8, (uint32_t)STAGE_B);
            TMA_LOAD_2D(slot, &tmA, p * BK, r0, sb + 16 + p * 8);
            TMA_LOAD_2D(slot + A_SZB, &tmB, p * BK, n0, sb + 16 + p * 8);
        }
    }

    float acc[4][4][4];
#pragma unroll
    for (int mf = 0; mf < 4; mf++)
#pragma unroll
        for (int nf = 0; nf < 4; nf++)
#pragma unroll
            for (int q = 0; q < 4; q++) acc[mf][nf][q] = 0.f;

#pragma unroll 4
    for (int c = 0; c < NCHUNK; c++) {
        int slot = c & 3;
        uint32_t mb = sb + 16 + slot * 8;
        MBARRIER_WAIT_PARITY(mb, (uint32_t)((c >> 2) & 1));

        const char* fA = smem + OFF_SLOT + slot * STAGE_B;
        const char* fB = fA + A_SZB;

        uint4 alo[4], ahi[4], bv[4];   // 8 halves each: phys k = 8*tig..+7
#pragma unroll
        for (int mf = 0; mf < 4; mf++) {
            int m0 = wm * 64 + mf * 16 + gid;
            alo[mf] = *(const uint4*)(fA + m0 * 64 + swt);
            ahi[mf] = *(const uint4*)(fA + (m0 + 8) * 64 + swt);
        }
#pragma unroll
        for (int nf = 0; nf < 4; nf++) {
            int nr = wn * 32 + nf * 8 + gid;
            bv[nf] = *(const uint4*)(fB + nr * 64 + swt);
        }
        __syncthreads();   // all warps consumed this slot
        if (c + 4 < NCHUNK && tid == 0) {
            uint32_t sdst = sb + OFF_SLOT + slot * STAGE_B;
            MBARRIER_EXPECT_TX(mb, (uint32_t)STAGE_B);
            TMA_LOAD_2D(sdst, &tmA, (c + 4) * BK, r0, mb);
            TMA_LOAD_2D(sdst + A_SZB, &tmB, (c + 4) * BK, n0, mb);
        }

        // instr 0: half-pairs 0,1 (phys k 8t..8t+3)
#pragma unroll
        for (int mf = 0; mf < 4; mf++)
#pragma unroll
            for (int nf = 0; nf < 4; nf++)
                mma_f16(acc[mf][nf], alo[mf].x, ahi[mf].x, alo[mf].y, ahi[mf].y,
                        bv[nf].x, bv[nf].y);
        // instr 1: half-pairs 2,3 (phys k 8t+4..8t+7)
#pragma unroll
        for (int mf = 0; mf < 4; mf++)
#pragma unroll
            for (int nf = 0; nf < 4; nf++)
                mma_f16(acc[mf][nf], alo[mf].z, ahi[mf].z, alo[mf].w, ahi[mf].w,
                        bv[nf].z, bv[nf].w);
    }
    __syncthreads();   // slots dead; red aliases slot 0

    // ---- epilogue: score partial = sum_n v[n] * tanh(acc + hp[n]) ----
    float* red = (float*)(smem + OFF_RED);  // [128][17]
#pragma unroll
    for (int mf = 0; mf < 4; mf++) {
#pragma unroll
        for (int half = 0; half < 2; half++) {
            int r = wm * 64 + mf * 16 + half * 8 + gid;
            float s = 0.f;
#pragma unroll
            for (int nf = 0; nf < 4; nf++) {
                int nl = wn * 32 + nf * 8 + tig * 2;
                float e0 = acc[mf][nf][half * 2 + 0] + shp[nl];
                float e1 = acc[mf][nf][half * 2 + 1] + shp[nl + 1];
                float t0, t1;
                asm("tanh.approx.f32 %0, %1;" : "=f"(t0) : "f"(e0));
                asm("tanh.approx.f32 %0, %1;" : "=f"(t1) : "f"(e1));
                s = fmaf(sv[nl], t0, s);
                s = fmaf(sv[nl + 1], t1, s);
            }
            red[r * 17 + wn * 4 + tig] = s;
        }
    }
    __syncthreads();
    if (tid < BM) {
        float s = 0.f;
#pragma unroll
        for (int t = 0; t < 16; t++) s += red[tid * 17 + t];
        g_pscore[nt * (BB * SS) + r0 + tid] = s;
    }
    __syncthreads();
    if (tid == 0) {
#pragma unroll
        for (int p = 0; p < 4; p++) MBARRIER_INVAL(sb + 16 + p * 8);
    }
}

// ---------------------------------------------------------------------------
// softmax: combine 4 partials, mask, softmax over S. grid(64), 512 threads.
// ---------------------------------------------------------------------------
__global__ void softmax_kernel(const int* __restrict__ mask,
                               float* __restrict__ wout) {
    int b = blockIdx.x;
    __shared__ float sc[SS];
    __shared__ float redbuf[512];
    int tid = threadIdx.x;

    float lmax = -3.402823466e38f;
    for (int s = tid; s < SS; s += 512) {
        int idx = b * SS + s;
        float v = g_pscore[idx] + g_pscore[BB * SS + idx] +
                  g_pscore[2 * BB * SS + idx] + g_pscore[3 * BB * SS + idx];
        if (mask[idx] == 0) v = -3.402823466e38f;
        sc[s] = v;
        lmax = fmaxf(lmax, v);
    }
    redbuf[tid] = lmax;
    __syncthreads();
    for (int o = 256; o > 0; o >>= 1) {
        if (tid < o) redbuf[tid] = fmaxf(redbuf[tid], redbuf[tid + o]);
        __syncthreads();
    }
    float m = redbuf[0];
    __syncthreads();

    float lsum = 0.f;
    for (int s = tid; s < SS; s += 512) {
        float e = expf(sc[s] - m);
        sc[s] = e;
        lsum += e;
    }
    redbuf[tid] = lsum;
    __syncthreads();
    for (int o = 256; o > 0; o >>= 1) {
        if (tid < o) redbuf[tid] += redbuf[tid + o];
        __syncthreads();
    }
    float inv = 1.f / redbuf[0];
    for (int s = tid; s < SS; s += 512) wout[b * SS + s] = sc[s] * inv;
}

// ---------------------------------------------------------------------------
// context partials from fp16 enc: grid (16, 64), 64 rows/slice, 128 threads.
// Two independent row streams per thread (r, r+32) -> 2x MLP.
// ---------------------------------------------------------------------------
__global__ void __launch_bounds__(128) context_part_kernel(
    const float* __restrict__ w) {
    __shared__ float ws[64];
    int sy = blockIdx.x, b = blockIdx.y;
    int e0 = threadIdx.x * 8;
    if (threadIdx.x < 64) ws[threadIdx.x] = w[b * SS + sy * 64 + threadIdx.x];
    __syncthreads();
    const __half* base0 = g_ench + ((size_t)b * SS + sy * 64) * EE + e0;
    const __half* base1 = base0 + (size_t)32 * EE;
    float acc0[8], acc1[8];
#pragma unroll
    for (int j = 0; j < 8; j++) { acc0[j] = 0.f; acc1[j] = 0.f; }
#pragma unroll 4
    for (int r = 0; r < 32; r++) {
        uint4 v0 = *(const uint4*)(base0 + (size_t)r * EE);
        uint4 v1 = *(const uint4*)(base1 + (size_t)r * EE);
        float c0 = ws[r], c1 = ws[r + 32];
        const uint32_t* p0 = (const uint32_t*)&v0;
        const uint32_t* p1 = (const uint32_t*)&v1;
#pragma unroll
        for (int q = 0; q < 4; q++) {
            float2 f0 = __half22float2(*(const __half2*)&p0[q]);
            float2 f1 = __half22float2(*(const __half2*)&p1[q]);
            acc0[q * 2 + 0] = fmaf(c0, f0.x, acc0[q * 2 + 0]);
            acc0[q * 2 + 1] = fmaf(c0, f0.y, acc0[q * 2 + 1]);
            acc1[q * 2 + 0] = fmaf(c1, f1.x, acc1[q * 2 + 0]);
            acc1[q * 2 + 1] = fmaf(c1, f1.y, acc1[q * 2 + 1]);
        }
    }
    float* dst = &g_ctx_part[((size_t)sy * BB + b) * EE + e0];
    *(float4*)dst = make_float4(acc0[0] + acc1[0], acc0[1] + acc1[1],
                                acc0[2] + acc1[2], acc0[3] + acc1[3]);
    *(float4*)(dst + 4) = make_float4(acc0[4] + acc1[4], acc0[5] + acc1[5],
                                      acc0[6] + acc1[6], acc0[7] + acc1[7]);
}

__global__ void context_reduce_kernel(float* __restrict__ ctx) {
    int b = blockIdx.y;
    int e = blockIdx.x * 256 + threadIdx.x;
    float s = 0.f;
#pragma unroll
    for (int sy = 0; sy < 16; sy++) s += g_ctx_part[((size_t)sy * BB + b) * EE + e];
    ctx[b * EE + e] = s;
}

// ---------------------------------------------------------------------------
// host: tensormap encode via driver entry point
// ---------------------------------------------------------------------------
typedef CUresult (*EncodeTiledFn)(
    CUtensorMap*, CUtensorMapDataType, cuuint32_t, void*,
    const cuuint64_t*, const cuuint64_t*, const cuuint32_t*, const cuuint32_t*,
    CUtensorMapInterleave, CUtensorMapSwizzle, CUtensorMapL2promotion,
    CUtensorMapFloatOOBfill);

static EncodeTiledFn get_encode_fn() {
    static EncodeTiledFn fn = nullptr;
    if (!fn) {
        void* p = nullptr;
        cudaDriverEntryPointQueryResult st;
#if CUDART_VERSION >= 12050
        cudaGetDriverEntryPointByVersion("cuTensorMapEncodeTiled", &p, 12000,
                                         cudaEnableDefault, &st);
#else
        cudaGetDriverEntryPoint("cuTensorMapEncodeTiled", &p, cudaEnableDefault, &st);
#endif
        fn = (EncodeTiledFn)p;
    }
    return fn;
}

static void make_tmap_f16(CUtensorMap* tm, void* ptr, uint64_t inner,
                          uint64_t outer, uint32_t box_inner, uint32_t box_outer) {
    cuuint64_t dims[2] = {inner, outer};
    cuuint64_t strides[1] = {inner * 2};
    cuuint32_t box[2] = {box_inner, box_outer};
    cuuint32_t es[2] = {1, 1};
    get_encode_fn()(tm, CU_TENSOR_MAP_DATA_TYPE_FLOAT16, 2, ptr, dims, strides,
                    box, es, CU_TENSOR_MAP_INTERLEAVE_NONE,
                    CU_TENSOR_MAP_SWIZZLE_64B, CU_TENSOR_MAP_L2_PROMOTION_L2_128B,
                    CU_TENSOR_MAP_FLOAT_OOB_FILL_NONE);
}

extern "C" void kernel_launch(void* const* d_in, const int* in_sizes, int n_in,
                              void* d_out, int out_size) {
    const float* hidden = (const float*)d_in[0];   // [B, D]
    const float* enc    = (const float*)d_in[1];   // [B, S, E2]
    const int*   mask   = (const int*)d_in[2];     // [B, S]
    const float* attn_W = (const float*)d_in[3];   // [E2+D, D]
    const float* attn_b = (const float*)d_in[4];   // [D]
    const float* v_W    = (const float*)d_in[5];   // [D]

    float* out = (float*)d_out;
    float* ctx = out;            // context [B, E2]
    float* wts = out + BB * EE;  // attn_weights [B, S]

    cudaFuncSetAttribute(scores_mma_kernel,
                         cudaFuncAttributeMaxDynamicSharedMemorySize, SMEM_SIZE);

    void* ench_ptr = nullptr; cudaGetSymbolAddress(&ench_ptr, g_ench);
    void* weth_ptr = nullptr; cudaGetSymbolAddress(&weth_ptr, g_WeTh);

    CUtensorMap tmA, tmB;
    make_tmap_f16(&tmA, ench_ptr, EE, (uint64_t)BB * SS, BK, BM);  // enc fp16 rows
    make_tmap_f16(&tmB, weth_ptr, EE, DD, BK, BN);                 // WeT fp16 rows

    prep_kernel<<<PREP_BLOCKS, 256>>>(enc, attn_W, attn_b, hidden);
    scores_mma_kernel<<<dim3(4, (BB * SS) / BM), 256, SMEM_SIZE>>>(tmA, tmB, v_W);
    softmax_kernel<<<BB, 512>>>(mask, wts);
    context_part_kernel<<<dim3(16, BB), 128>>>(wts);
    context_reduce_kernel<<<dim3(4, BB), 256>>>(ctx);
}